// round 1
// baseline (speedup 1.0000x reference)
#include <cuda_runtime.h>

#define Dm   1024
#define Hn   16
#define HD   64
#define Bb   4
#define Tt   2048
#define BH   (Bb*Hn)

// Scratch for Q,K,V in [B*H, T, hd] layout (32 MB each)
__device__ float g_Q[(size_t)BH * Tt * HD];
__device__ float g_K[(size_t)BH * Tt * HD];
__device__ float g_V[(size_t)BH * Tt * HD];

// ---------------------------------------------------------------------------
// Projection: out[b,h,t,d] = sum_k X[b,t,k] * W[h*64+d, k] + bias[h*64+d]
// 128x128 tile, BK=8, 256 threads, 8x8 per-thread microtile, fp32.
// blockIdx.z selects Q/K/V.
// ---------------------------------------------------------------------------
__global__ __launch_bounds__(256) void proj_kernel(
    const float* __restrict__ X,
    const float* __restrict__ Wq, const float* __restrict__ bq,
    const float* __restrict__ Wk, const float* __restrict__ bk,
    const float* __restrict__ Wv, const float* __restrict__ bv)
{
    const float* W; const float* bias; float* out;
    if (blockIdx.z == 0)      { W = Wq; bias = bq; out = g_Q; }
    else if (blockIdx.z == 1) { W = Wk; bias = bk; out = g_K; }
    else                      { W = Wv; bias = bv; out = g_V; }

    __shared__ float Xs[8][132];
    __shared__ float Ws[8][132];

    const int tid = threadIdx.x;
    const int m0 = blockIdx.x * 128;
    const int n0 = blockIdx.y * 128;

    const int lr = tid >> 1;          // 0..127 row within tile
    const int lk = (tid & 1) << 2;    // 0 or 4
    const float* Xp = X + (size_t)(m0 + lr) * Dm + lk;
    const float* Wp = W + (size_t)(n0 + lr) * Dm + lk;

    float acc[8][8];
#pragma unroll
    for (int i = 0; i < 8; i++)
#pragma unroll
        for (int j = 0; j < 8; j++) acc[i][j] = 0.f;

    const int r = tid >> 4, c = tid & 15;
    const int i0 = r * 8, j0 = c * 8;

    float4 xv = *(const float4*)(Xp);
    float4 wv = *(const float4*)(Wp);

    for (int k0 = 0; k0 < Dm; k0 += 8) {
        Xs[lk + 0][lr] = xv.x; Xs[lk + 1][lr] = xv.y;
        Xs[lk + 2][lr] = xv.z; Xs[lk + 3][lr] = xv.w;
        Ws[lk + 0][lr] = wv.x; Ws[lk + 1][lr] = wv.y;
        Ws[lk + 2][lr] = wv.z; Ws[lk + 3][lr] = wv.w;
        __syncthreads();

        if (k0 + 8 < Dm) {
            xv = *(const float4*)(Xp + k0 + 8);
            wv = *(const float4*)(Wp + k0 + 8);
        }

#pragma unroll
        for (int kk = 0; kk < 8; kk++) {
            float a[8], bb[8];
            *(float4*)&a[0]  = *(const float4*)&Xs[kk][i0];
            *(float4*)&a[4]  = *(const float4*)&Xs[kk][i0 + 4];
            *(float4*)&bb[0] = *(const float4*)&Ws[kk][j0];
            *(float4*)&bb[4] = *(const float4*)&Ws[kk][j0 + 4];
#pragma unroll
            for (int ii = 0; ii < 8; ii++)
#pragma unroll
                for (int jj = 0; jj < 8; jj++)
                    acc[ii][jj] += a[ii] * bb[jj];
        }
        __syncthreads();
    }

    // Epilogue: scatter into [B*H, T, hd] layout
#pragma unroll
    for (int ii = 0; ii < 8; ii++) {
        int m = m0 + i0 + ii;
        int b = m >> 11;          // / 2048
        int t = m & 2047;
#pragma unroll
        for (int jj = 0; jj < 8; jj += 4) {
            int n = n0 + j0 + jj;
            int h = n >> 6;
            int d = n & 63;
            float4 o;
            o.x = acc[ii][jj + 0] + bias[n + 0];
            o.y = acc[ii][jj + 1] + bias[n + 1];
            o.z = acc[ii][jj + 2] + bias[n + 2];
            o.w = acc[ii][jj + 3] + bias[n + 3];
            *(float4*)&out[((size_t)((b << 4) + h) * Tt + t) * HD + d] = o;
        }
    }
}

// ---------------------------------------------------------------------------
// Flash attention, fp32, causal. BQ=BKV=64, hd=64, 256 threads (16x16),
// 4x4 microtiles for both S=Q·K^T and O+=P·V. Online softmax with
// half-warp shfl reductions. Scale = +8 (faithful to reference bug).
// ---------------------------------------------------------------------------
__global__ __launch_bounds__(256) void attn_kernel(float* __restrict__ out)
{
    extern __shared__ float sm[];
    float* Qt = sm;                // [64][68]  Q transposed (d-major)
    float* Kt = Qt + 64 * 68;      // [64][68]  K transposed (d-major)
    float* Vs = Kt + 64 * 68;      // [64][64]  V row-major
    float* Pt = Vs + 64 * 64;      // [64][68]  P transposed (kv-major)

    const int tid = threadIdx.x;
    const int qi  = blockIdx.x;    // q tile 0..31
    const int bh  = blockIdx.y;    // 0..63
    const float* Qg = g_Q + (size_t)bh * Tt * HD;
    const float* Kg = g_K + (size_t)bh * Tt * HD;
    const float* Vg = g_V + (size_t)bh * Tt * HD;
    const int q0 = qi * 64;

    // Load Q tile transposed: Qt[d][i] = Q[q0+i][d]
    for (int idx = tid; idx < 64 * 16; idx += 256) {
        int row = idx >> 4;
        int dc  = (idx & 15) << 2;
        float4 v = *(const float4*)(Qg + (size_t)(q0 + row) * HD + dc);
        Qt[(dc + 0) * 68 + row] = v.x;
        Qt[(dc + 1) * 68 + row] = v.y;
        Qt[(dc + 2) * 68 + row] = v.z;
        Qt[(dc + 3) * 68 + row] = v.w;
    }

    const int r = tid >> 4, c = tid & 15;
    const int i0 = r << 2, j0 = c << 2;

    float m_i[4], l_i[4], accO[4][4];
#pragma unroll
    for (int ii = 0; ii < 4; ii++) {
        m_i[ii] = -1e30f; l_i[ii] = 0.f;
#pragma unroll
        for (int dd = 0; dd < 4; dd++) accO[ii][dd] = 0.f;
    }

    for (int kt = 0; kt <= qi; kt++) {
        const int k0 = kt * 64;
        __syncthreads();  // previous iter's readers of Kt/Vs/Pt done

        // Load K transposed + V row-major
        for (int idx = tid; idx < 64 * 16; idx += 256) {
            int row = idx >> 4;
            int dc  = (idx & 15) << 2;
            float4 kv = *(const float4*)(Kg + (size_t)(k0 + row) * HD + dc);
            Kt[(dc + 0) * 68 + row] = kv.x;
            Kt[(dc + 1) * 68 + row] = kv.y;
            Kt[(dc + 2) * 68 + row] = kv.z;
            Kt[(dc + 3) * 68 + row] = kv.w;
            float4 vv = *(const float4*)(Vg + (size_t)(k0 + row) * HD + dc);
            *(float4*)&Vs[row * HD + dc] = vv;
        }
        __syncthreads();

        // S = Q · K^T (4x4 per thread), contract over d
        float S[4][4];
#pragma unroll
        for (int ii = 0; ii < 4; ii++)
#pragma unroll
            for (int jj = 0; jj < 4; jj++) S[ii][jj] = 0.f;

#pragma unroll 8
        for (int d = 0; d < 64; d++) {
            float a[4], bb[4];
            *(float4*)a  = *(const float4*)&Qt[d * 68 + i0];
            *(float4*)bb = *(const float4*)&Kt[d * 68 + j0];
#pragma unroll
            for (int ii = 0; ii < 4; ii++)
#pragma unroll
                for (int jj = 0; jj < 4; jj++)
                    S[ii][jj] += a[ii] * bb[jj];
        }

        // Scale by +8 (faithful bug) and apply causal mask on diagonal tile
        const bool diag = (kt == qi);
#pragma unroll
        for (int ii = 0; ii < 4; ii++)
#pragma unroll
            for (int jj = 0; jj < 4; jj++) {
                float s = S[ii][jj] * 8.0f;
                if (diag && (j0 + jj) > (i0 + ii)) s = -1e30f;
                S[ii][jj] = s;
            }

        // Online softmax per row (reduce across the 16 threads of the row)
#pragma unroll
        for (int ii = 0; ii < 4; ii++) {
            float mx = fmaxf(fmaxf(S[ii][0], S[ii][1]), fmaxf(S[ii][2], S[ii][3]));
#pragma unroll
            for (int off = 8; off > 0; off >>= 1)
                mx = fmaxf(mx, __shfl_xor_sync(0xffffffffu, mx, off));
            float mnew = fmaxf(m_i[ii], mx);
            float corr = __expf(m_i[ii] - mnew);
            m_i[ii] = mnew;
            float rs = 0.f;
#pragma unroll
            for (int jj = 0; jj < 4; jj++) {
                float p = __expf(S[ii][jj] - mnew);
                S[ii][jj] = p;
                rs += p;
            }
#pragma unroll
            for (int off = 8; off > 0; off >>= 1)
                rs += __shfl_xor_sync(0xffffffffu, rs, off);
            l_i[ii] = l_i[ii] * corr + rs;
#pragma unroll
            for (int dd = 0; dd < 4; dd++) accO[ii][dd] *= corr;
        }

        // Stage P transposed for the PV GEMM
#pragma unroll
        for (int ii = 0; ii < 4; ii++)
#pragma unroll
            for (int jj = 0; jj < 4; jj++)
                Pt[(j0 + jj) * 68 + (i0 + ii)] = S[ii][jj];
        __syncthreads();

        // O += P · V
#pragma unroll 8
        for (int j = 0; j < 64; j++) {
            float a[4], v4[4];
            *(float4*)a  = *(const float4*)&Pt[j * 68 + i0];
            *(float4*)v4 = *(const float4*)&Vs[j * HD + j0];
#pragma unroll
            for (int ii = 0; ii < 4; ii++)
#pragma unroll
                for (int dd = 0; dd < 4; dd++)
                    accO[ii][dd] += a[ii] * v4[dd];
        }
    }

    // Epilogue: normalize and write to [B, T, H*hd]
    const int b = bh >> 4, h = bh & 15;
#pragma unroll
    for (int ii = 0; ii < 4; ii++) {
        float inv = 1.0f / l_i[ii];
        int q = q0 + i0 + ii;
        float4 o;
        o.x = accO[ii][0] * inv;
        o.y = accO[ii][1] * inv;
        o.z = accO[ii][2] * inv;
        o.w = accO[ii][3] * inv;
        *(float4*)&out[((size_t)(b * Tt + q)) * Dm + h * HD + j0] = o;
    }
}

// ---------------------------------------------------------------------------
extern "C" void kernel_launch(void* const* d_in, const int* in_sizes, int n_in,
                              void* d_out, int out_size)
{
    (void)in_sizes; (void)n_in; (void)out_size;
    const float* x  = (const float*)d_in[0];
    const float* Wq = (const float*)d_in[1];
    const float* bq = (const float*)d_in[2];
    const float* Wk = (const float*)d_in[3];
    const float* bk = (const float*)d_in[4];
    const float* Wv = (const float*)d_in[5];
    const float* bv = (const float*)d_in[6];
    float* out = (float*)d_out;

    dim3 pg(64, 8, 3);  // 8192/128 M-tiles, 1024/128 N-tiles, {Q,K,V}
    proj_kernel<<<pg, 256>>>(x, Wq, bq, Wk, bk, Wv, bv);

    const int SMEM = (64 * 68 * 3 + 64 * 64) * (int)sizeof(float);  // 68608 B
    cudaFuncSetAttribute(attn_kernel,
                         cudaFuncAttributeMaxDynamicSharedMemorySize, SMEM);
    attn_kernel<<<dim3(32, 64), 256, SMEM>>>(out);
}

// round 3
// speedup vs baseline: 1.4507x; 1.4507x over previous
#include <cuda_runtime.h>
#include <cuda_bf16.h>
#include <cstdint>

#define Dm   1024
#define Hn   16
#define HD   64
#define Bb   4
#define Tt   2048
#define BH   (Bb*Hn)
#define Mtot (Bb*Tt)

// Scratch: Q,K,V in [B*H, T, hd] layout (32 MB each)
__device__ float g_Q[(size_t)BH * Tt * HD];
__device__ float g_K[(size_t)BH * Tt * HD];
__device__ float g_V[(size_t)BH * Tt * HD];
// Split-bf16 operands
__device__ __nv_bfloat16 g_Xh[(size_t)Mtot * Dm];
__device__ __nv_bfloat16 g_Xl[(size_t)Mtot * Dm];
__device__ __nv_bfloat16 g_Wh[(size_t)3 * Dm * Dm];
__device__ __nv_bfloat16 g_Wl[(size_t)3 * Dm * Dm];

// ---------------------------------------------------------------------------
// Baseline-PTX helpers (NO tcgen05 — harness compiles for plain sm_103)
// ---------------------------------------------------------------------------
__device__ __forceinline__ uint32_t smem_u32(const void* p) {
    uint32_t a;
    asm("{ .reg .u64 t; cvta.to.shared.u64 t, %1; cvt.u32.u64 %0, t; }"
        : "=r"(a) : "l"(p));
    return a;
}
__device__ __forceinline__ void cpa16(uint32_t s, const void* g) {
    asm volatile("cp.async.cg.shared.global [%0], [%1], 16;" :: "r"(s), "l"(g));
}
#define CP_COMMIT() asm volatile("cp.async.commit_group;" ::: "memory")
#define CP_WAIT(n)  asm volatile("cp.async.wait_group %0;" :: "n"(n) : "memory")

__device__ __forceinline__ void ldsm_x4(uint32_t& r0, uint32_t& r1,
                                        uint32_t& r2, uint32_t& r3, uint32_t a) {
    asm volatile("ldmatrix.sync.aligned.m8n8.x4.shared.b16 {%0,%1,%2,%3}, [%4];"
                 : "=r"(r0), "=r"(r1), "=r"(r2), "=r"(r3) : "r"(a));
}
__device__ __forceinline__ void mma16816(float* c, const uint32_t* a,
                                         uint32_t b0, uint32_t b1) {
    asm volatile(
        "mma.sync.aligned.m16n8k16.row.col.f32.bf16.bf16.f32 "
        "{%0,%1,%2,%3}, {%4,%5,%6,%7}, {%8,%9}, {%0,%1,%2,%3};"
        : "+f"(c[0]), "+f"(c[1]), "+f"(c[2]), "+f"(c[3])
        : "r"(a[0]), "r"(a[1]), "r"(a[2]), "r"(a[3]), "r"(b0), "r"(b1));
}

// ---------------------------------------------------------------------------
// Split fp32 -> (hi, lo) bf16
// ---------------------------------------------------------------------------
__global__ __launch_bounds__(256) void split_kernel(
    const float* __restrict__ in, __nv_bfloat16* __restrict__ hi,
    __nv_bfloat16* __restrict__ lo, int n4)
{
    int i = blockIdx.x * 256 + threadIdx.x;
    if (i >= n4) return;
    float4 v = ((const float4*)in)[i];
    float f[4] = {v.x, v.y, v.z, v.w};
    unsigned short h[4], l[4];
#pragma unroll
    for (int j = 0; j < 4; j++) {
        __nv_bfloat16 hb = __float2bfloat16(f[j]);
        __nv_bfloat16 lb = __float2bfloat16(f[j] - __bfloat162float(hb));
        h[j] = __bfloat16_as_ushort(hb);
        l[j] = __bfloat16_as_ushort(lb);
    }
    ((ushort4*)hi)[i] = make_ushort4(h[0], h[1], h[2], h[3]);
    ((ushort4*)lo)[i] = make_ushort4(l[0], l[1], l[2], l[3]);
}

// ---------------------------------------------------------------------------
// Projection GEMM via mma.sync (HMMA) split-bf16.
// out[M=8192, N=1024] = X @ W^T + b.
// CTA tile 128x128, warp tile 64x32 (2x4 warps), BK=64, double-buffered
// cp.async pipeline. acc += Ah*Bh + Al*Bh + Ah*Bl (fp32 accumulate).
// ---------------------------------------------------------------------------
#define BK      64
#define NSTAGE  (Dm / BK)          // 16
#define PITCHE  72                 // row pitch in bf16 elements (144 B)
#define PITCHB  144
#define TILE_B  (128 * PITCHB)     // 18432 B per operand tile
#define STG_B   (4 * TILE_B)       // Ah,Al,Bh,Bl = 73728 B per stage
#define GEMM_SMEM (2 * STG_B)      // 147456 B

__global__ __launch_bounds__(256) void proj_mma_kernel(
    const float* __restrict__ bq, const float* __restrict__ bk,
    const float* __restrict__ bv)
{
    extern __shared__ char smem[];
    const int tid  = threadIdx.x;
    const int z    = blockIdx.z;
    const int m0   = blockIdx.x * 128;
    const int n0   = blockIdx.y * 128;

    const uint4* Xh4 = (const uint4*)g_Xh;
    const uint4* Xl4 = (const uint4*)g_Xl;
    const uint4* Wh4 = (const uint4*)(g_Wh + (size_t)z * Dm * Dm);
    const uint4* Wl4 = (const uint4*)(g_Wl + (size_t)z * Dm * Dm);
    const float* bias = (z == 0) ? bq : (z == 1) ? bk : bv;
    float* out = (z == 0) ? g_Q : (z == 1) ? g_K : g_V;

    const uint32_t sb = smem_u32(smem);

    // per-thread load slots: 4 uint4 per operand tile
    const int lrow = tid >> 1;              // not used; see below
    (void)lrow;

    // load index mapping: idx in [0,1024) per tile; row = idx>>3, seg = idx&7
    // thread handles idx = tid + 256*j, j=0..3
    // gmem uint4 row stride = Dm/8 = 128

    // fragment addressing (per warp)
    const int warp = tid >> 5, lane = tid & 31;
    const int wm = warp >> 2;               // 0..1
    const int wn = warp & 3;                // 0..3
    const int a_row = wm * 64 + (lane & 7) + ((lane >> 3) & 1) * 8;
    const uint32_t a_kb = ((lane >> 4) & 1) * 16;
    const int b_row = wn * 32 + (lane & 7) + ((lane >> 4) & 1) * 8;
    const uint32_t b_kb = ((lane >> 3) & 1) * 16;

    float acc[4][4][4];
#pragma unroll
    for (int i = 0; i < 4; i++)
#pragma unroll
        for (int j = 0; j < 4; j++)
#pragma unroll
            for (int k = 0; k < 4; k++) acc[i][j][k] = 0.f;

    // ---- pipeline: issue stage s loads into buffer s&1 ----
    auto issue_stage = [&](int s) {
        const uint32_t base = sb + (s & 1) * STG_B;
        const int kseg0 = s * (BK / 8);     // uint4 offset within K row
#pragma unroll
        for (int j = 0; j < 4; j++) {
            int idx = tid + 256 * j;
            int row = idx >> 3, seg = idx & 7;
            uint32_t so = (uint32_t)(row * PITCHB + seg * 16);
            size_t ga = (size_t)(m0 + row) * 128 + kseg0 + seg;
            size_t gb = (size_t)(n0 + row) * 128 + kseg0 + seg;
            cpa16(base + so,              Xh4 + ga);
            cpa16(base + TILE_B + so,     Xl4 + ga);
            cpa16(base + 2 * TILE_B + so, Wh4 + gb);
            cpa16(base + 3 * TILE_B + so, Wl4 + gb);
        }
        CP_COMMIT();
    };

    issue_stage(0);

    for (int s = 0; s < NSTAGE; s++) {
        if (s + 1 < NSTAGE) {
            issue_stage(s + 1);
            CP_WAIT(1);
        } else {
            CP_WAIT(0);
        }
        __syncthreads();

        const uint32_t base = sb + (s & 1) * STG_B;
        const uint32_t Ah = base, Al = base + TILE_B;
        const uint32_t Bh = base + 2 * TILE_B, Bl = base + 3 * TILE_B;

#pragma unroll
        for (int ks = 0; ks < BK / 16; ks++) {
            const uint32_t ko = ks * 32;
            uint32_t ah[4][4], al[4][4], bh[2][4], bl[2][4];
#pragma unroll
            for (int ma = 0; ma < 4; ma++) {
                uint32_t ao = (uint32_t)((a_row + ma * 16) * PITCHB) + ko + a_kb;
                ldsm_x4(ah[ma][0], ah[ma][1], ah[ma][2], ah[ma][3], Ah + ao);
                ldsm_x4(al[ma][0], al[ma][1], al[ma][2], al[ma][3], Al + ao);
            }
#pragma unroll
            for (int pb = 0; pb < 2; pb++) {
                uint32_t bo = (uint32_t)((b_row + pb * 16) * PITCHB) + ko + b_kb;
                ldsm_x4(bh[pb][0], bh[pb][1], bh[pb][2], bh[pb][3], Bh + bo);
                ldsm_x4(bl[pb][0], bl[pb][1], bl[pb][2], bl[pb][3], Bl + bo);
            }
#pragma unroll
            for (int ma = 0; ma < 4; ma++)
#pragma unroll
                for (int na = 0; na < 4; na++) {
                    const int pb = na >> 1, hi = (na & 1) * 2;
                    mma16816(acc[ma][na], ah[ma], bh[pb][hi], bh[pb][hi + 1]);
                    mma16816(acc[ma][na], al[ma], bh[pb][hi], bh[pb][hi + 1]);
                    mma16816(acc[ma][na], ah[ma], bl[pb][hi], bl[pb][hi + 1]);
                }
        }
        __syncthreads();
    }

    // ---- epilogue: add bias, scatter fp32 to [B*H, T, hd] ----
    const int gid = lane >> 2, tig = lane & 3;
#pragma unroll
    for (int ma = 0; ma < 4; ma++) {
        const int row0 = m0 + wm * 64 + ma * 16 + gid;
#pragma unroll
        for (int na = 0; na < 4; na++) {
            const int col = n0 + wn * 32 + na * 8 + tig * 2;
            const float2 bv2 = *(const float2*)&bias[col];
            const int h = col >> 6, d = col & 63;
#pragma unroll
            for (int half = 0; half < 2; half++) {
                const int row = row0 + half * 8;
                const int b = row >> 11, t = row & 2047;
                float2 o;
                o.x = acc[ma][na][half * 2 + 0] + bv2.x;
                o.y = acc[ma][na][half * 2 + 1] + bv2.y;
                *(float2*)&out[((size_t)((b << 4) + h) * Tt + t) * HD + d] = o;
            }
        }
    }
}

// ---------------------------------------------------------------------------
// Flash attention (R1 version — measured ~92% of fp32 FFMA ceiling)
// ---------------------------------------------------------------------------
__global__ __launch_bounds__(256) void attn_kernel(float* __restrict__ out)
{
    extern __shared__ float sm[];
    float* Qt = sm;
    float* Kt = Qt + 64 * 68;
    float* Vs = Kt + 64 * 68;
    float* Pt = Vs + 64 * 64;

    const int tid = threadIdx.x;
    const int qi  = blockIdx.x;
    const int bh  = blockIdx.y;
    const float* Qg = g_Q + (size_t)bh * Tt * HD;
    const float* Kg = g_K + (size_t)bh * Tt * HD;
    const float* Vg = g_V + (size_t)bh * Tt * HD;
    const int q0 = qi * 64;

    for (int idx = tid; idx < 64 * 16; idx += 256) {
        int row = idx >> 4;
        int dc  = (idx & 15) << 2;
        float4 v = *(const float4*)(Qg + (size_t)(q0 + row) * HD + dc);
        Qt[(dc + 0) * 68 + row] = v.x;
        Qt[(dc + 1) * 68 + row] = v.y;
        Qt[(dc + 2) * 68 + row] = v.z;
        Qt[(dc + 3) * 68 + row] = v.w;
    }

    const int r = tid >> 4, c = tid & 15;
    const int i0 = r << 2, j0 = c << 2;

    float m_i[4], l_i[4], accO[4][4];
#pragma unroll
    for (int ii = 0; ii < 4; ii++) {
        m_i[ii] = -1e30f; l_i[ii] = 0.f;
#pragma unroll
        for (int dd = 0; dd < 4; dd++) accO[ii][dd] = 0.f;
    }

    for (int kt = 0; kt <= qi; kt++) {
        const int k0 = kt * 64;
        __syncthreads();

        for (int idx = tid; idx < 64 * 16; idx += 256) {
            int row = idx >> 4;
            int dc  = (idx & 15) << 2;
            float4 kv = *(const float4*)(Kg + (size_t)(k0 + row) * HD + dc);
            Kt[(dc + 0) * 68 + row] = kv.x;
            Kt[(dc + 1) * 68 + row] = kv.y;
            Kt[(dc + 2) * 68 + row] = kv.z;
            Kt[(dc + 3) * 68 + row] = kv.w;
            float4 vv = *(const float4*)(Vg + (size_t)(k0 + row) * HD + dc);
            *(float4*)&Vs[row * HD + dc] = vv;
        }
        __syncthreads();

        float S[4][4];
#pragma unroll
        for (int ii = 0; ii < 4; ii++)
#pragma unroll
            for (int jj = 0; jj < 4; jj++) S[ii][jj] = 0.f;

#pragma unroll 8
        for (int d = 0; d < 64; d++) {
            float a[4], bb[4];
            *(float4*)a  = *(const float4*)&Qt[d * 68 + i0];
            *(float4*)bb = *(const float4*)&Kt[d * 68 + j0];
#pragma unroll
            for (int ii = 0; ii < 4; ii++)
#pragma unroll
                for (int jj = 0; jj < 4; jj++)
                    S[ii][jj] += a[ii] * bb[jj];
        }

        const bool diag = (kt == qi);
#pragma unroll
        for (int ii = 0; ii < 4; ii++)
#pragma unroll
            for (int jj = 0; jj < 4; jj++) {
                float s = S[ii][jj] * 8.0f;
                if (diag && (j0 + jj) > (i0 + ii)) s = -1e30f;
                S[ii][jj] = s;
            }

#pragma unroll
        for (int ii = 0; ii < 4; ii++) {
            float mx = fmaxf(fmaxf(S[ii][0], S[ii][1]), fmaxf(S[ii][2], S[ii][3]));
#pragma unroll
            for (int off = 8; off > 0; off >>= 1)
                mx = fmaxf(mx, __shfl_xor_sync(0xffffffffu, mx, off));
            float mnew = fmaxf(m_i[ii], mx);
            float corr = __expf(m_i[ii] - mnew);
            m_i[ii] = mnew;
            float rs = 0.f;
#pragma unroll
            for (int jj = 0; jj < 4; jj++) {
                float p = __expf(S[ii][jj] - mnew);
                S[ii][jj] = p;
                rs += p;
            }
#pragma unroll
            for (int off = 8; off > 0; off >>= 1)
                rs += __shfl_xor_sync(0xffffffffu, rs, off);
            l_i[ii] = l_i[ii] * corr + rs;
#pragma unroll
            for (int dd = 0; dd < 4; dd++) accO[ii][dd] *= corr;
        }

#pragma unroll
        for (int ii = 0; ii < 4; ii++)
#pragma unroll
            for (int jj = 0; jj < 4; jj++)
                Pt[(j0 + jj) * 68 + (i0 + ii)] = S[ii][jj];
        __syncthreads();

#pragma unroll 8
        for (int j = 0; j < 64; j++) {
            float a[4], v4[4];
            *(float4*)a  = *(const float4*)&Pt[j * 68 + i0];
            *(float4*)v4 = *(const float4*)&Vs[j * HD + j0];
#pragma unroll
            for (int ii = 0; ii < 4; ii++)
#pragma unroll
                for (int dd = 0; dd < 4; dd++)
                    accO[ii][dd] += a[ii] * v4[dd];
        }
    }

    const int b = bh >> 4, h = bh & 15;
#pragma unroll
    for (int ii = 0; ii < 4; ii++) {
        float inv = 1.0f / l_i[ii];
        int q = q0 + i0 + ii;
        float4 o;
        o.x = accO[ii][0] * inv;
        o.y = accO[ii][1] * inv;
        o.z = accO[ii][2] * inv;
        o.w = accO[ii][3] * inv;
        *(float4*)&out[((size_t)(b * Tt + q)) * Dm + h * HD + j0] = o;
    }
}

// ---------------------------------------------------------------------------
extern "C" void kernel_launch(void* const* d_in, const int* in_sizes, int n_in,
                              void* d_out, int out_size)
{
    (void)in_sizes; (void)n_in; (void)out_size;
    const float* x  = (const float*)d_in[0];
    const float* Wq = (const float*)d_in[1];
    const float* bq = (const float*)d_in[2];
    const float* Wk = (const float*)d_in[3];
    const float* bk = (const float*)d_in[4];
    const float* Wv = (const float*)d_in[5];
    const float* bv = (const float*)d_in[6];
    float* out = (float*)d_out;

    __nv_bfloat16 *xh, *xl, *wh, *wl;
    cudaGetSymbolAddress((void**)&xh, g_Xh);
    cudaGetSymbolAddress((void**)&xl, g_Xl);
    cudaGetSymbolAddress((void**)&wh, g_Wh);
    cudaGetSymbolAddress((void**)&wl, g_Wl);

    const int nX4 = Mtot * Dm / 4;
    const int nW4 = Dm * Dm / 4;
    split_kernel<<<(nX4 + 255) / 256, 256>>>(x, xh, xl, nX4);
    split_kernel<<<(nW4 + 255) / 256, 256>>>(Wq, wh,             wl,             nW4);
    split_kernel<<<(nW4 + 255) / 256, 256>>>(Wk, wh + 1 * Dm*Dm, wl + 1 * Dm*Dm, nW4);
    split_kernel<<<(nW4 + 255) / 256, 256>>>(Wv, wh + 2 * Dm*Dm, wl + 2 * Dm*Dm, nW4);

    cudaFuncSetAttribute(proj_mma_kernel,
                         cudaFuncAttributeMaxDynamicSharedMemorySize, GEMM_SMEM);
    dim3 pg(Mtot / 128, Dm / 128, 3);   // 64 x 8 x 3
    proj_mma_kernel<<<pg, 256, GEMM_SMEM>>>(bq, bk, bv);

    const int SMEM = (64 * 68 * 3 + 64 * 64) * (int)sizeof(float);
    cudaFuncSetAttribute(attn_kernel,
                         cudaFuncAttributeMaxDynamicSharedMemorySize, SMEM);
    attn_kernel<<<dim3(32, 64), 256, SMEM>>>(out);
}

// round 4
// speedup vs baseline: 2.7515x; 1.8967x over previous
#include <cuda_runtime.h>
#include <cuda_bf16.h>
#include <cstdint>

#define Dm   1024
#define Hn   16
#define HD   64
#define Bb   4
#define Tt   2048
#define BH   (Bb*Hn)
#define Mtot (Bb*Tt)

// Split-bf16 GEMM operands
__device__ __nv_bfloat16 g_Xh[(size_t)Mtot * Dm];
__device__ __nv_bfloat16 g_Xl[(size_t)Mtot * Dm];
__device__ __nv_bfloat16 g_Wh[(size_t)3 * Dm * Dm];
__device__ __nv_bfloat16 g_Wl[(size_t)3 * Dm * Dm];
// Projection outputs, split bf16. Q pre-scaled by 8. V transposed [bh][d][t].
__device__ __nv_bfloat16 g_Qh[(size_t)BH * Tt * HD];
__device__ __nv_bfloat16 g_Ql[(size_t)BH * Tt * HD];
__device__ __nv_bfloat16 g_Kh[(size_t)BH * Tt * HD];
__device__ __nv_bfloat16 g_Kl[(size_t)BH * Tt * HD];
__device__ __nv_bfloat16 g_VtH[(size_t)BH * HD * Tt];
__device__ __nv_bfloat16 g_VtL[(size_t)BH * HD * Tt];

// ---------------------------------------------------------------------------
__device__ __forceinline__ uint32_t smem_u32(const void* p) {
    uint32_t a;
    asm("{ .reg .u64 t; cvta.to.shared.u64 t, %1; cvt.u32.u64 %0, t; }"
        : "=r"(a) : "l"(p));
    return a;
}
__device__ __forceinline__ void cpa16(uint32_t s, const void* g) {
    asm volatile("cp.async.cg.shared.global [%0], [%1], 16;" :: "r"(s), "l"(g));
}
#define CP_COMMIT() asm volatile("cp.async.commit_group;" ::: "memory")
#define CP_WAIT(n)  asm volatile("cp.async.wait_group %0;" :: "n"(n) : "memory")

__device__ __forceinline__ void ldsm_x4(uint32_t& r0, uint32_t& r1,
                                        uint32_t& r2, uint32_t& r3, uint32_t a) {
    asm volatile("ldmatrix.sync.aligned.m8n8.x4.shared.b16 {%0,%1,%2,%3}, [%4];"
                 : "=r"(r0), "=r"(r1), "=r"(r2), "=r"(r3) : "r"(a));
}
__device__ __forceinline__ void mma16816(float* c, const uint32_t* a,
                                         uint32_t b0, uint32_t b1) {
    asm volatile(
        "mma.sync.aligned.m16n8k16.row.col.f32.bf16.bf16.f32 "
        "{%0,%1,%2,%3}, {%4,%5,%6,%7}, {%8,%9}, {%0,%1,%2,%3};"
        : "+f"(c[0]), "+f"(c[1]), "+f"(c[2]), "+f"(c[3])
        : "r"(a[0]), "r"(a[1]), "r"(a[2]), "r"(a[3]), "r"(b0), "r"(b1));
}
// pack two floats -> bf16x2 (lo = a, hi = b)
__device__ __forceinline__ uint32_t packbf2(float a, float b) {
    uint32_t r;
    asm("cvt.rn.bf16x2.f32 %0, %1, %2;" : "=r"(r) : "f"(b), "f"(a));
    return r;
}

// ---------------------------------------------------------------------------
// Split fp32 -> (hi, lo) bf16
// ---------------------------------------------------------------------------
__global__ __launch_bounds__(256) void split_kernel(
    const float* __restrict__ in, __nv_bfloat16* __restrict__ hi,
    __nv_bfloat16* __restrict__ lo, int n4)
{
    int i = blockIdx.x * 256 + threadIdx.x;
    if (i >= n4) return;
    float4 v = ((const float4*)in)[i];
    float f[4] = {v.x, v.y, v.z, v.w};
    unsigned short h[4], l[4];
#pragma unroll
    for (int j = 0; j < 4; j++) {
        __nv_bfloat16 hb = __float2bfloat16(f[j]);
        __nv_bfloat16 lb = __float2bfloat16(f[j] - __bfloat162float(hb));
        h[j] = __bfloat16_as_ushort(hb);
        l[j] = __bfloat16_as_ushort(lb);
    }
    ((ushort4*)hi)[i] = make_ushort4(h[0], h[1], h[2], h[3]);
    ((ushort4*)lo)[i] = make_ushort4(l[0], l[1], l[2], l[3]);
}

// ---------------------------------------------------------------------------
// Projection GEMM (HMMA, split-bf16). Epilogue emits split-bf16 Q/K ([bh][t][d],
// Q pre-scaled by 8) and transposed split-bf16 V ([bh][d][t]).
// ---------------------------------------------------------------------------
#define BK      64
#define NSTAGE  (Dm / BK)
#define PITCHB  144
#define TILE_B  (128 * PITCHB)
#define STG_B   (4 * TILE_B)
#define GEMM_SMEM (2 * STG_B)

__global__ __launch_bounds__(256) void proj_mma_kernel(
    const float* __restrict__ bq, const float* __restrict__ bk,
    const float* __restrict__ bv)
{
    extern __shared__ char smem[];
    const int tid  = threadIdx.x;
    const int z    = blockIdx.z;
    const int m0   = blockIdx.x * 128;
    const int n0   = blockIdx.y * 128;

    const uint4* Xh4 = (const uint4*)g_Xh;
    const uint4* Xl4 = (const uint4*)g_Xl;
    const uint4* Wh4 = (const uint4*)(g_Wh + (size_t)z * Dm * Dm);
    const uint4* Wl4 = (const uint4*)(g_Wl + (size_t)z * Dm * Dm);
    const float* bias = (z == 0) ? bq : (z == 1) ? bk : bv;
    __nv_bfloat16* OutH = (z == 0) ? g_Qh : g_Kh;
    __nv_bfloat16* OutL = (z == 0) ? g_Ql : g_Kl;

    const uint32_t sb = smem_u32(smem);
    const int warp = tid >> 5, lane = tid & 31;
    const int wm = warp >> 2;
    const int wn = warp & 3;
    const int a_row = wm * 64 + (lane & 7) + ((lane >> 3) & 1) * 8;
    const uint32_t a_kb = ((lane >> 4) & 1) * 16;
    const int b_row = wn * 32 + (lane & 7) + ((lane >> 4) & 1) * 8;
    const uint32_t b_kb = ((lane >> 3) & 1) * 16;

    float acc[4][4][4];
#pragma unroll
    for (int i = 0; i < 4; i++)
#pragma unroll
        for (int j = 0; j < 4; j++)
#pragma unroll
            for (int k = 0; k < 4; k++) acc[i][j][k] = 0.f;

    auto issue_stage = [&](int s) {
        const uint32_t base = sb + (s & 1) * STG_B;
        const int kseg0 = s * (BK / 8);
#pragma unroll
        for (int j = 0; j < 4; j++) {
            int idx = tid + 256 * j;
            int row = idx >> 3, seg = idx & 7;
            uint32_t so = (uint32_t)(row * PITCHB + seg * 16);
            size_t ga = (size_t)(m0 + row) * 128 + kseg0 + seg;
            size_t gb = (size_t)(n0 + row) * 128 + kseg0 + seg;
            cpa16(base + so,              Xh4 + ga);
            cpa16(base + TILE_B + so,     Xl4 + ga);
            cpa16(base + 2 * TILE_B + so, Wh4 + gb);
            cpa16(base + 3 * TILE_B + so, Wl4 + gb);
        }
        CP_COMMIT();
    };

    issue_stage(0);

    for (int s = 0; s < NSTAGE; s++) {
        if (s + 1 < NSTAGE) { issue_stage(s + 1); CP_WAIT(1); }
        else                { CP_WAIT(0); }
        __syncthreads();

        const uint32_t base = sb + (s & 1) * STG_B;
        const uint32_t Ah = base, Al = base + TILE_B;
        const uint32_t Bh = base + 2 * TILE_B, Bl = base + 3 * TILE_B;

#pragma unroll
        for (int ks = 0; ks < BK / 16; ks++) {
            const uint32_t ko = ks * 32;
            uint32_t ah[4][4], al[4][4], bh[2][4], bl[2][4];
#pragma unroll
            for (int ma = 0; ma < 4; ma++) {
                uint32_t ao = (uint32_t)((a_row + ma * 16) * PITCHB) + ko + a_kb;
                ldsm_x4(ah[ma][0], ah[ma][1], ah[ma][2], ah[ma][3], Ah + ao);
                ldsm_x4(al[ma][0], al[ma][1], al[ma][2], al[ma][3], Al + ao);
            }
#pragma unroll
            for (int pb = 0; pb < 2; pb++) {
                uint32_t bo = (uint32_t)((b_row + pb * 16) * PITCHB) + ko + b_kb;
                ldsm_x4(bh[pb][0], bh[pb][1], bh[pb][2], bh[pb][3], Bh + bo);
                ldsm_x4(bl[pb][0], bl[pb][1], bl[pb][2], bl[pb][3], Bl + bo);
            }
            // split OUTERMOST: 16 independent accumulators between reuse
#pragma unroll
            for (int sp = 0; sp < 3; sp++) {
#pragma unroll
                for (int ma = 0; ma < 4; ma++)
#pragma unroll
                    for (int na = 0; na < 4; na++) {
                        const int pb = na >> 1, hb = (na & 1) * 2;
                        const uint32_t* af = (sp == 1) ? al[ma] : ah[ma];
                        const uint32_t (*bf)[4] = (sp == 2) ? bl : bh;
                        mma16816(acc[ma][na], af, bf[pb][hb], bf[pb][hb + 1]);
                    }
            }
        }
        __syncthreads();
    }

    // epilogue: +bias, (Q: x8), split to bf16 hi/lo; Q/K [bh][t][d], V^T [bh][d][t]
    const int gid = lane >> 2, tig = lane & 3;
    const float qscale = (z == 0) ? 8.0f : 1.0f;
#pragma unroll
    for (int ma = 0; ma < 4; ma++) {
#pragma unroll
        for (int na = 0; na < 4; na++) {
            const int col = n0 + wn * 32 + na * 8 + tig * 2;
            const float2 bv2 = *(const float2*)&bias[col];
            const int hh = col >> 6, d = col & 63;
#pragma unroll
            for (int half = 0; half < 2; half++) {
                const int row = m0 + wm * 64 + ma * 16 + gid + half * 8;
                const int b = row >> 11, t = row & 2047;
                const int bhidx = (b << 4) + hh;
                float v0 = (acc[ma][na][half * 2 + 0] + bv2.x) * qscale;
                float v1 = (acc[ma][na][half * 2 + 1] + bv2.y) * qscale;
                __nv_bfloat16 h0 = __float2bfloat16(v0);
                __nv_bfloat16 h1 = __float2bfloat16(v1);
                __nv_bfloat16 l0 = __float2bfloat16(v0 - __bfloat162float(h0));
                __nv_bfloat16 l1 = __float2bfloat16(v1 - __bfloat162float(h1));
                if (z < 2) {
                    size_t ix = ((size_t)bhidx * Tt + t) * HD + d;
                    uint32_t ph = ((uint32_t)__bfloat16_as_ushort(h1) << 16) |
                                   __bfloat16_as_ushort(h0);
                    uint32_t pl = ((uint32_t)__bfloat16_as_ushort(l1) << 16) |
                                   __bfloat16_as_ushort(l0);
                    *(uint32_t*)&OutH[ix] = ph;
                    *(uint32_t*)&OutL[ix] = pl;
                } else {
                    size_t ix = ((size_t)bhidx * HD + d) * Tt + t;
                    g_VtH[ix]      = h0;  g_VtH[ix + Tt] = h1;
                    g_VtL[ix]      = l0;  g_VtL[ix + Tt] = l1;
                }
            }
        }
    }
}

// ---------------------------------------------------------------------------
// Flash attention, HMMA split-bf16. BQ=128 (8 warps x M16), BKV=64.
// S = QhKh + QlKh + QhKl (Q pre-scaled x8). O += PhVh + PlVh + PhVl.
// ---------------------------------------------------------------------------
#define AQ_B   (128 * PITCHB)          // 18432 per Q array
#define AT_B   (64 * PITCHB)           // 9216 per K/V tile array
#define ASTG_B (4 * AT_B)              // Kh,Kl,Vh,Vl per stage
#define ATTN_SMEM (2 * AQ_B + 2 * ASTG_B)   // 110592

__global__ __launch_bounds__(256) void attn_mma_kernel(float* __restrict__ out)
{
    extern __shared__ char smem[];
    const int tid  = threadIdx.x;
    const int w    = tid >> 5, lane = tid & 31;
    const int qi   = (int)gridDim.x - 1 - (int)blockIdx.x;   // long CTAs first
    const int bh   = blockIdx.y;
    const int q0   = qi * 128;
    const int n_kv = 2 * (qi + 1);

    const uint32_t sb  = smem_u32(smem);
    const uint32_t sQh = sb, sQl = sb + AQ_B;
    const uint32_t sT0 = sb + 2 * AQ_B;

    const int gid = lane >> 2, tig = lane & 3;
    const int arow = (lane & 7) + ((lane >> 3) & 1) * 8;
    const uint32_t akb = ((lane >> 4) & 1) * 16;
    const int brow = (lane & 7) + ((lane >> 4) & 1) * 8;
    const uint32_t bkb = ((lane >> 3) & 1) * 16;

    // ---- async loads ----
    {   // Q: 128 rows x 64 bf16 (hi+lo)
#pragma unroll
        for (int j = 0; j < 4; j++) {
            int idx = tid + 256 * j;
            int row = idx >> 3, seg = idx & 7;
            uint32_t so = (uint32_t)(row * PITCHB + seg * 16);
            size_t g = ((size_t)bh * Tt + q0 + row) * HD + seg * 8;
            cpa16(sQh + so, g_Qh + g);
            cpa16(sQl + so, g_Ql + g);
        }
    }
    auto loadKV = [&](int kt) {
        const uint32_t base = sT0 + (kt & 1) * ASTG_B;
        const int k0 = kt * 64;
#pragma unroll
        for (int j = 0; j < 2; j++) {
            int idx = tid + 256 * j;
            int row = idx >> 3, seg = idx & 7;
            uint32_t so = (uint32_t)(row * PITCHB + seg * 16);
            size_t gk = ((size_t)bh * Tt + k0 + row) * HD + seg * 8;
            size_t gv = ((size_t)bh * HD + row) * Tt + k0 + seg * 8;
            cpa16(base + so,            g_Kh + gk);
            cpa16(base + AT_B + so,     g_Kl + gk);
            cpa16(base + 2 * AT_B + so, g_VtH + gv);
            cpa16(base + 3 * AT_B + so, g_VtL + gv);
        }
        CP_COMMIT();
    };

    loadKV(0);            // group0: Q + KV0 (Q issued before, same group)
    loadKV(1);            // group1

    uint32_t qh[4][4], ql[4][4];
    bool qloaded = false;

    float m0r = -1e30f, m1r = -1e30f, l0r = 0.f, l1r = 0.f;
    float accO[8][4];
#pragma unroll
    for (int na = 0; na < 8; na++)
#pragma unroll
        for (int j = 0; j < 4; j++) accO[na][j] = 0.f;

    for (int kt = 0; kt < n_kv; kt++) {
        if (kt + 1 < n_kv) { CP_WAIT(1); } else { CP_WAIT(0); }
        __syncthreads();

        if (!qloaded) {
#pragma unroll
            for (int ks = 0; ks < 4; ks++) {
                uint32_t ao = (uint32_t)((w * 16 + arow) * PITCHB) + ks * 32 + akb;
                ldsm_x4(qh[ks][0], qh[ks][1], qh[ks][2], qh[ks][3], sQh + ao);
                ldsm_x4(ql[ks][0], ql[ks][1], ql[ks][2], ql[ks][3], sQl + ao);
            }
            qloaded = true;
        }

        const uint32_t base = sT0 + (kt & 1) * ASTG_B;
        const int k0 = kt * 64;

        // ---- S = Q K^T ----
        float s[8][4];
#pragma unroll
        for (int na = 0; na < 8; na++)
#pragma unroll
            for (int j = 0; j < 4; j++) s[na][j] = 0.f;

#pragma unroll
        for (int ks = 0; ks < 4; ks++) {
            uint32_t kh[4][4], kl[4][4];
#pragma unroll
            for (int pb = 0; pb < 4; pb++) {
                uint32_t bo = (uint32_t)((pb * 16 + brow) * PITCHB) + ks * 32 + bkb;
                ldsm_x4(kh[pb][0], kh[pb][1], kh[pb][2], kh[pb][3], base + bo);
                ldsm_x4(kl[pb][0], kl[pb][1], kl[pb][2], kl[pb][3], base + AT_B + bo);
            }
#pragma unroll
            for (int sp = 0; sp < 3; sp++) {
                const uint32_t* af = (sp == 1) ? ql[ks] : qh[ks];
                const uint32_t (*bf)[4] = (sp == 2) ? kl : kh;
#pragma unroll
                for (int na = 0; na < 8; na++)
                    mma16816(s[na], af, bf[na >> 1][(na & 1) * 2],
                                        bf[na >> 1][(na & 1) * 2 + 1]);
            }
        }

        // ---- causal mask (only near the diagonal) ----
        const int r0 = q0 + w * 16 + gid, r1 = r0 + 8;
        if (k0 + 63 > r0) {
#pragma unroll
            for (int na = 0; na < 8; na++) {
                int c0 = k0 + na * 8 + tig * 2, c1 = c0 + 1;
                if (c0 > r0) s[na][0] = -1e30f;
                if (c1 > r0) s[na][1] = -1e30f;
                if (c0 > r1) s[na][2] = -1e30f;
                if (c1 > r1) s[na][3] = -1e30f;
            }
        }

        // ---- online softmax ----
        float mx0 = -1e30f, mx1 = -1e30f;
#pragma unroll
        for (int na = 0; na < 8; na++) {
            mx0 = fmaxf(mx0, fmaxf(s[na][0], s[na][1]));
            mx1 = fmaxf(mx1, fmaxf(s[na][2], s[na][3]));
        }
        mx0 = fmaxf(mx0, __shfl_xor_sync(0xffffffffu, mx0, 1));
        mx0 = fmaxf(mx0, __shfl_xor_sync(0xffffffffu, mx0, 2));
        mx1 = fmaxf(mx1, __shfl_xor_sync(0xffffffffu, mx1, 1));
        mx1 = fmaxf(mx1, __shfl_xor_sync(0xffffffffu, mx1, 2));
        float mn0 = fmaxf(m0r, mx0), mn1 = fmaxf(m1r, mx1);
        float c0f = __expf(m0r - mn0), c1f = __expf(m1r - mn1);
        m0r = mn0; m1r = mn1;

        float rs0 = 0.f, rs1 = 0.f;
        uint32_t ph[8], ph2[8], pl[8], pl2[8];
#pragma unroll
        for (int na = 0; na < 8; na++) {
            float p0 = __expf(s[na][0] - mn0);
            float p1 = __expf(s[na][1] - mn0);
            float p2 = __expf(s[na][2] - mn1);
            float p3 = __expf(s[na][3] - mn1);
            rs0 += p0 + p1; rs1 += p2 + p3;
            __nv_bfloat16 h0 = __float2bfloat16(p0), h1 = __float2bfloat16(p1);
            __nv_bfloat16 h2 = __float2bfloat16(p2), h3 = __float2bfloat16(p3);
            ph[na]  = ((uint32_t)__bfloat16_as_ushort(h1) << 16) | __bfloat16_as_ushort(h0);
            ph2[na] = ((uint32_t)__bfloat16_as_ushort(h3) << 16) | __bfloat16_as_ushort(h2);
            pl[na]  = packbf2(p0 - __bfloat162float(h0), p1 - __bfloat162float(h1));
            pl2[na] = packbf2(p2 - __bfloat162float(h2), p3 - __bfloat162float(h3));
        }
        rs0 += __shfl_xor_sync(0xffffffffu, rs0, 1);
        rs0 += __shfl_xor_sync(0xffffffffu, rs0, 2);
        rs1 += __shfl_xor_sync(0xffffffffu, rs1, 1);
        rs1 += __shfl_xor_sync(0xffffffffu, rs1, 2);
        l0r = l0r * c0f + rs0;
        l1r = l1r * c1f + rs1;
#pragma unroll
        for (int na = 0; na < 8; na++) {
            accO[na][0] *= c0f; accO[na][1] *= c0f;
            accO[na][2] *= c1f; accO[na][3] *= c1f;
        }

        // ---- O += P V ----
        const uint32_t vb = base + 2 * AT_B;
#pragma unroll
        for (int ks = 0; ks < 4; ks++) {
            uint32_t vh[4][4], vl[4][4];
#pragma unroll
            for (int pb = 0; pb < 4; pb++) {
                uint32_t bo = (uint32_t)((pb * 16 + brow) * PITCHB) + ks * 32 + bkb;
                ldsm_x4(vh[pb][0], vh[pb][1], vh[pb][2], vh[pb][3], vb + bo);
                ldsm_x4(vl[pb][0], vl[pb][1], vl[pb][2], vl[pb][3], vb + AT_B + bo);
            }
            uint32_t a_h[4] = {ph[2 * ks], ph2[2 * ks], ph[2 * ks + 1], ph2[2 * ks + 1]};
            uint32_t a_l[4] = {pl[2 * ks], pl2[2 * ks], pl[2 * ks + 1], pl2[2 * ks + 1]};
#pragma unroll
            for (int na = 0; na < 8; na++)
                mma16816(accO[na], a_h, vh[na >> 1][(na & 1) * 2],
                                        vh[na >> 1][(na & 1) * 2 + 1]);
#pragma unroll
            for (int na = 0; na < 8; na++)
                mma16816(accO[na], a_l, vh[na >> 1][(na & 1) * 2],
                                        vh[na >> 1][(na & 1) * 2 + 1]);
#pragma unroll
            for (int na = 0; na < 8; na++)
                mma16816(accO[na], a_h, vl[na >> 1][(na & 1) * 2],
                                        vl[na >> 1][(na & 1) * 2 + 1]);
        }

        if (kt + 2 < n_kv) {
            __syncthreads();      // buffer (kt&1) free across all warps
            loadKV(kt + 2);
        }
    }

    // ---- epilogue ----
    const int b = bh >> 4, hh = bh & 15;
    const float inv0 = 1.0f / l0r, inv1 = 1.0f / l1r;
    const int r0 = q0 + w * 16 + gid, r1 = r0 + 8;
#pragma unroll
    for (int na = 0; na < 8; na++) {
        const int col = hh * 64 + na * 8 + tig * 2;
        float2 o0 = make_float2(accO[na][0] * inv0, accO[na][1] * inv0);
        float2 o1 = make_float2(accO[na][2] * inv1, accO[na][3] * inv1);
        *(float2*)&out[((size_t)(b * Tt + r0)) * Dm + col] = o0;
        *(float2*)&out[((size_t)(b * Tt + r1)) * Dm + col] = o1;
    }
}

// ---------------------------------------------------------------------------
extern "C" void kernel_launch(void* const* d_in, const int* in_sizes, int n_in,
                              void* d_out, int out_size)
{
    (void)in_sizes; (void)n_in; (void)out_size;
    const float* x  = (const float*)d_in[0];
    const float* Wq = (const float*)d_in[1];
    const float* bq = (const float*)d_in[2];
    const float* Wk = (const float*)d_in[3];
    const float* bk = (const float*)d_in[4];
    const float* Wv = (const float*)d_in[5];
    const float* bv = (const float*)d_in[6];
    float* out = (float*)d_out;

    __nv_bfloat16 *xh, *xl, *wh, *wl;
    cudaGetSymbolAddress((void**)&xh, g_Xh);
    cudaGetSymbolAddress((void**)&xl, g_Xl);
    cudaGetSymbolAddress((void**)&wh, g_Wh);
    cudaGetSymbolAddress((void**)&wl, g_Wl);

    const int nX4 = Mtot * Dm / 4;
    const int nW4 = Dm * Dm / 4;
    split_kernel<<<(nX4 + 255) / 256, 256>>>(x, xh, xl, nX4);
    split_kernel<<<(nW4 + 255) / 256, 256>>>(Wq, wh,             wl,             nW4);
    split_kernel<<<(nW4 + 255) / 256, 256>>>(Wk, wh + 1 * Dm*Dm, wl + 1 * Dm*Dm, nW4);
    split_kernel<<<(nW4 + 255) / 256, 256>>>(Wv, wh + 2 * Dm*Dm, wl + 2 * Dm*Dm, nW4);

    cudaFuncSetAttribute(proj_mma_kernel,
                         cudaFuncAttributeMaxDynamicSharedMemorySize, GEMM_SMEM);
    dim3 pg(Mtot / 128, Dm / 128, 3);
    proj_mma_kernel<<<pg, 256, GEMM_SMEM>>>(bq, bk, bv);

    cudaFuncSetAttribute(attn_mma_kernel,
                         cudaFuncAttributeMaxDynamicSharedMemorySize, ATTN_SMEM);
    attn_mma_kernel<<<dim3(16, 64), 256, ATTN_SMEM>>>(out);
}

// round 5
// speedup vs baseline: 2.9187x; 1.0608x over previous
#include <cuda_runtime.h>
#include <cuda_bf16.h>
#include <cstdint>

#define Dm   1024
#define Hn   16
#define HD   64
#define Bb   4
#define Tt   2048
#define BH   (Bb*Hn)
#define Mtot (Bb*Tt)
#define NX4  (Mtot*Dm/4)
#define NW4  (Dm*Dm/4)

// Split-bf16 GEMM operands
__device__ __nv_bfloat16 g_Xh[(size_t)Mtot * Dm];
__device__ __nv_bfloat16 g_Xl[(size_t)Mtot * Dm];
__device__ __nv_bfloat16 g_Wh[(size_t)3 * Dm * Dm];
__device__ __nv_bfloat16 g_Wl[(size_t)3 * Dm * Dm];
// Projection outputs, split bf16. Q pre-scaled by 8*log2(e). V^T [bh][d][t].
__device__ __nv_bfloat16 g_Qh[(size_t)BH * Tt * HD];
__device__ __nv_bfloat16 g_Ql[(size_t)BH * Tt * HD];
__device__ __nv_bfloat16 g_Kh[(size_t)BH * Tt * HD];
__device__ __nv_bfloat16 g_Kl[(size_t)BH * Tt * HD];
__device__ __nv_bfloat16 g_VtH[(size_t)BH * HD * Tt];
__device__ __nv_bfloat16 g_VtL[(size_t)BH * HD * Tt];

// ---------------------------------------------------------------------------
__device__ __forceinline__ uint32_t smem_u32(const void* p) {
    uint32_t a;
    asm("{ .reg .u64 t; cvta.to.shared.u64 t, %1; cvt.u32.u64 %0, t; }"
        : "=r"(a) : "l"(p));
    return a;
}
__device__ __forceinline__ void cpa16(uint32_t s, const void* g) {
    asm volatile("cp.async.cg.shared.global [%0], [%1], 16;" :: "r"(s), "l"(g));
}
#define CP_COMMIT() asm volatile("cp.async.commit_group;" ::: "memory")
#define CP_WAIT(n)  asm volatile("cp.async.wait_group %0;" :: "n"(n) : "memory")

__device__ __forceinline__ void ldsm_x4(uint32_t& r0, uint32_t& r1,
                                        uint32_t& r2, uint32_t& r3, uint32_t a) {
    asm volatile("ldmatrix.sync.aligned.m8n8.x4.shared.b16 {%0,%1,%2,%3}, [%4];"
                 : "=r"(r0), "=r"(r1), "=r"(r2), "=r"(r3) : "r"(a));
}
__device__ __forceinline__ void mma16816(float* c, const uint32_t* a,
                                         uint32_t b0, uint32_t b1) {
    asm volatile(
        "mma.sync.aligned.m16n8k16.row.col.f32.bf16.bf16.f32 "
        "{%0,%1,%2,%3}, {%4,%5,%6,%7}, {%8,%9}, {%0,%1,%2,%3};"
        : "+f"(c[0]), "+f"(c[1]), "+f"(c[2]), "+f"(c[3])
        : "r"(a[0]), "r"(a[1]), "r"(a[2]), "r"(a[3]), "r"(b0), "r"(b1));
}
__device__ __forceinline__ uint32_t packbf2(float a, float b) {
    uint32_t r;
    asm("cvt.rn.bf16x2.f32 %0, %1, %2;" : "=r"(r) : "f"(b), "f"(a));
    return r;
}

// ---------------------------------------------------------------------------
// Merged split: X, Wq, Wk, Wv -> (hi, lo) bf16 in one launch
// ---------------------------------------------------------------------------
__global__ __launch_bounds__(256) void split_all(
    const float* __restrict__ x, const float* __restrict__ wq,
    const float* __restrict__ wk, const float* __restrict__ wv)
{
    int i = blockIdx.x * 256 + threadIdx.x;
    const float4* src;
    ushort4 *hi, *lo;
    if (i < NX4) {
        src = (const float4*)x + i;
        hi = (ushort4*)g_Xh + i;
        lo = (ushort4*)g_Xl + i;
    } else {
        int j = i - NX4;
        int w = j >> 18;                 // NW4 = 2^18
        int o = j & (NW4 - 1);
        const float* ws = (w == 0) ? wq : (w == 1) ? wk : wv;
        src = (const float4*)ws + o;
        hi = (ushort4*)(g_Wh + (size_t)w * Dm * Dm) + o;
        lo = (ushort4*)(g_Wl + (size_t)w * Dm * Dm) + o;
    }
    float4 v = *src;
    float f[4] = {v.x, v.y, v.z, v.w};
    unsigned short h[4], l[4];
#pragma unroll
    for (int j = 0; j < 4; j++) {
        __nv_bfloat16 hb = __float2bfloat16(f[j]);
        __nv_bfloat16 lb = __float2bfloat16(f[j] - __bfloat162float(hb));
        h[j] = __bfloat16_as_ushort(hb);
        l[j] = __bfloat16_as_ushort(lb);
    }
    *hi = make_ushort4(h[0], h[1], h[2], h[3]);
    *lo = make_ushort4(l[0], l[1], l[2], l[3]);
}

// ---------------------------------------------------------------------------
// Projection GEMM (HMMA split-bf16). 128x128 tile, BK=32, 2-stage cp.async,
// 2 CTAs/SM. Staged fragment loads keep regs under the 128 cap.
// ---------------------------------------------------------------------------
#define BKp      32
#define NSTp     (Dm / BKp)         // 32
#define PITCH_P  80
#define TILE_P   (128 * PITCH_P)    // 10240
#define STG_P    (4 * TILE_P)       // 40960
#define GEMM_SMEM (2 * STG_P)       // 81920

__global__ __launch_bounds__(256, 2) void proj_mma_kernel(
    const float* __restrict__ bq, const float* __restrict__ bk,
    const float* __restrict__ bv)
{
    extern __shared__ char smem[];
    const int tid  = threadIdx.x;
    const int z    = blockIdx.z;
    const int m0   = blockIdx.x * 128;
    const int n0   = blockIdx.y * 128;

    const uint4* Xh4 = (const uint4*)g_Xh;
    const uint4* Xl4 = (const uint4*)g_Xl;
    const uint4* Wh4 = (const uint4*)(g_Wh + (size_t)z * Dm * Dm);
    const uint4* Wl4 = (const uint4*)(g_Wl + (size_t)z * Dm * Dm);
    const float* bias = (z == 0) ? bq : (z == 1) ? bk : bv;
    __nv_bfloat16* OutH = (z == 0) ? g_Qh : g_Kh;
    __nv_bfloat16* OutL = (z == 0) ? g_Ql : g_Kl;

    const uint32_t sb = smem_u32(smem);
    const int warp = tid >> 5, lane = tid & 31;
    const int wm = warp >> 2;
    const int wn = warp & 3;
    const int a_row = wm * 64 + (lane & 7) + ((lane >> 3) & 1) * 8;
    const uint32_t a_kb = ((lane >> 4) & 1) * 16;
    const int b_row = wn * 32 + (lane & 7) + ((lane >> 4) & 1) * 8;
    const uint32_t b_kb = ((lane >> 3) & 1) * 16;

    float acc[4][4][4];
#pragma unroll
    for (int i = 0; i < 4; i++)
#pragma unroll
        for (int j = 0; j < 4; j++)
#pragma unroll
            for (int k = 0; k < 4; k++) acc[i][j][k] = 0.f;

    // stage loads: each array 128 rows x 4 segs(16B) = 512 cp.async
    auto issue_stage = [&](int s) {
        const uint32_t base = sb + (s & 1) * STG_P;
        const int kseg0 = s * (BKp / 8);
#pragma unroll
        for (int j = 0; j < 2; j++) {
            int idx = tid + 256 * j;
            int row = idx >> 2, seg = idx & 3;
            uint32_t so = (uint32_t)(row * PITCH_P + seg * 16);
            size_t ga = (size_t)(m0 + row) * 128 + kseg0 + seg;
            size_t gb = (size_t)(n0 + row) * 128 + kseg0 + seg;
            cpa16(base + so,              Xh4 + ga);
            cpa16(base + TILE_P + so,     Xl4 + ga);
            cpa16(base + 2 * TILE_P + so, Wh4 + gb);
            cpa16(base + 3 * TILE_P + so, Wl4 + gb);
        }
        CP_COMMIT();
    };

    issue_stage(0);

    for (int s = 0; s < NSTp; s++) {
        if (s + 1 < NSTp) { issue_stage(s + 1); CP_WAIT(1); }
        else              { CP_WAIT(0); }
        __syncthreads();

        const uint32_t base = sb + (s & 1) * STG_P;
        const uint32_t Ah = base, Al = base + TILE_P;
        const uint32_t Bh = base + 2 * TILE_P, Bl = base + 3 * TILE_P;

#pragma unroll
        for (int ks = 0; ks < 2; ks++) {
            const uint32_t ko = ks * 32;
            uint32_t af[4][4], tf[4][4], bf[2][4];
#pragma unroll
            for (int ma = 0; ma < 4; ma++) {
                uint32_t ao = (uint32_t)((a_row + ma * 16) * PITCH_P) + ko + a_kb;
                ldsm_x4(af[ma][0], af[ma][1], af[ma][2], af[ma][3], Ah + ao);
            }
#pragma unroll
            for (int pb = 0; pb < 2; pb++) {
                uint32_t bo = (uint32_t)((b_row + pb * 16) * PITCH_P) + ko + b_kb;
                ldsm_x4(bf[pb][0], bf[pb][1], bf[pb][2], bf[pb][3], Bh + bo);
            }
#pragma unroll
            for (int ma = 0; ma < 4; ma++)
#pragma unroll
                for (int na = 0; na < 4; na++)
                    mma16816(acc[ma][na], af[ma],
                             bf[na >> 1][(na & 1) * 2], bf[na >> 1][(na & 1) * 2 + 1]);
            // lo(A) x hi(B)
#pragma unroll
            for (int ma = 0; ma < 4; ma++) {
                uint32_t ao = (uint32_t)((a_row + ma * 16) * PITCH_P) + ko + a_kb;
                ldsm_x4(tf[ma][0], tf[ma][1], tf[ma][2], tf[ma][3], Al + ao);
            }
#pragma unroll
            for (int ma = 0; ma < 4; ma++)
#pragma unroll
                for (int na = 0; na < 4; na++)
                    mma16816(acc[ma][na], tf[ma],
                             bf[na >> 1][(na & 1) * 2], bf[na >> 1][(na & 1) * 2 + 1]);
            // hi(A) x lo(B) — overwrite bf
#pragma unroll
            for (int pb = 0; pb < 2; pb++) {
                uint32_t bo = (uint32_t)((b_row + pb * 16) * PITCH_P) + ko + b_kb;
                ldsm_x4(bf[pb][0], bf[pb][1], bf[pb][2], bf[pb][3], Bl + bo);
            }
#pragma unroll
            for (int ma = 0; ma < 4; ma++)
#pragma unroll
                for (int na = 0; na < 4; na++)
                    mma16816(acc[ma][na], af[ma],
                             bf[na >> 1][(na & 1) * 2], bf[na >> 1][(na & 1) * 2 + 1]);
        }
        __syncthreads();
    }

    // epilogue: +bias, (Q: x 8*log2e), split to bf16 hi/lo
    const int gid = lane >> 2, tig = lane & 3;
    const float qscale = (z == 0) ? 11.541560327111707f : 1.0f;   // 8*log2(e)
#pragma unroll
    for (int ma = 0; ma < 4; ma++) {
#pragma unroll
        for (int na = 0; na < 4; na++) {
            const int col = n0 + wn * 32 + na * 8 + tig * 2;
            const float2 bv2 = *(const float2*)&bias[col];
            const int hh = col >> 6, d = col & 63;
#pragma unroll
            for (int half = 0; half < 2; half++) {
                const int row = m0 + wm * 64 + ma * 16 + gid + half * 8;
                const int b = row >> 11, t = row & 2047;
                const int bhidx = (b << 4) + hh;
                float v0 = (acc[ma][na][half * 2 + 0] + bv2.x) * qscale;
                float v1 = (acc[ma][na][half * 2 + 1] + bv2.y) * qscale;
                __nv_bfloat16 h0 = __float2bfloat16(v0);
                __nv_bfloat16 h1 = __float2bfloat16(v1);
                __nv_bfloat16 l0 = __float2bfloat16(v0 - __bfloat162float(h0));
                __nv_bfloat16 l1 = __float2bfloat16(v1 - __bfloat162float(h1));
                if (z < 2) {
                    size_t ix = ((size_t)bhidx * Tt + t) * HD + d;
                    uint32_t ph = ((uint32_t)__bfloat16_as_ushort(h1) << 16) |
                                   __bfloat16_as_ushort(h0);
                    uint32_t pl = ((uint32_t)__bfloat16_as_ushort(l1) << 16) |
                                   __bfloat16_as_ushort(l0);
                    *(uint32_t*)&OutH[ix] = ph;
                    *(uint32_t*)&OutL[ix] = pl;
                } else {
                    size_t ix = ((size_t)bhidx * HD + d) * Tt + t;
                    g_VtH[ix]      = h0;  g_VtH[ix + Tt] = h1;
                    g_VtL[ix]      = l0;  g_VtL[ix + Tt] = l1;
                }
            }
        }
    }
}

// ---------------------------------------------------------------------------
// Flash attention, HMMA split-bf16, base-2 softmax (Q pre-scaled 8*log2e).
// BQ=128 (8 warps x M16), BKV=32, 3-stage cp.async ring, 2 CTAs/SM.
// ---------------------------------------------------------------------------
#define PITCHQ  144
#define AQ_B    (128 * PITCHQ)        // 18432 per Q array
#define KT_B    (32 * PITCHQ)         // 4608 per K array (32 t-rows x 64 d)
#define VT_B    (64 * 80)             // 5120 per V array (64 d-rows x 32 t)
#define ASTG_B  (2 * KT_B + 2 * VT_B) // 19456
#define ATTN_SMEM (2 * AQ_B + 3 * ASTG_B)   // 95232

__global__ __launch_bounds__(256, 2) void attn_mma_kernel(float* __restrict__ out)
{
    extern __shared__ char smem[];
    const int tid  = threadIdx.x;
    const int w    = tid >> 5, lane = tid & 31;
    const int qi   = (int)gridDim.x - 1 - (int)blockIdx.x;   // long CTAs first
    const int bh   = blockIdx.y;
    const int q0   = qi * 128;
    const int n_kv = 4 * (qi + 1);

    const uint32_t sb  = smem_u32(smem);
    const uint32_t sQh = sb, sQl = sb + AQ_B;
    const uint32_t sT0 = sb + 2 * AQ_B;

    const int gid = lane >> 2, tig = lane & 3;
    const int arow = (lane & 7) + ((lane >> 3) & 1) * 8;
    const uint32_t akb = ((lane >> 4) & 1) * 16;
    const int brow = (lane & 7) + ((lane >> 4) & 1) * 8;
    const uint32_t bkb = ((lane >> 3) & 1) * 16;

    // Q: 128 rows x 64 bf16 (hi+lo) — part of commit group 0
#pragma unroll
    for (int j = 0; j < 4; j++) {
        int idx = tid + 256 * j;
        int row = idx >> 3, seg = idx & 7;
        uint32_t so = (uint32_t)(row * PITCHQ + seg * 16);
        size_t g = ((size_t)bh * Tt + q0 + row) * HD + seg * 8;
        cpa16(sQh + so, g_Qh + g);
        cpa16(sQl + so, g_Ql + g);
    }
    auto loadKV = [&](int kt) {
        const uint32_t base = sT0 + (kt % 3) * ASTG_B;
        const int k0 = kt * 32;
        {   // K: 32 rows(t) x 8 segs
            int row = tid >> 3, seg = tid & 7;
            if (tid < 256) {
                uint32_t so = (uint32_t)(row * PITCHQ + seg * 16);
                size_t gk = ((size_t)bh * Tt + k0 + row) * HD + seg * 8;
                cpa16(base + so,        g_Kh + gk);
                cpa16(base + KT_B + so, g_Kl + gk);
            }
        }
        {   // V^T: 64 rows(d) x 4 segs
            int row = tid >> 2, seg = tid & 3;
            uint32_t so = (uint32_t)(row * 80 + seg * 16);
            size_t gv = ((size_t)bh * HD + row) * Tt + k0 + seg * 8;
            cpa16(base + 2 * KT_B + so,        g_VtH + gv);
            cpa16(base + 2 * KT_B + VT_B + so, g_VtL + gv);
        }
        CP_COMMIT();
    };

    loadKV(0);
    loadKV(1);
    loadKV(2);

    float m0r = -1e30f, m1r = -1e30f, l0r = 0.f, l1r = 0.f;
    float accO[8][4];
#pragma unroll
    for (int na = 0; na < 8; na++)
#pragma unroll
        for (int j = 0; j < 4; j++) accO[na][j] = 0.f;

    for (int kt = 0; kt < n_kv; kt++) {
        if (kt + 2 < n_kv)      { CP_WAIT(2); }
        else if (kt + 1 < n_kv) { CP_WAIT(1); }
        else                    { CP_WAIT(0); }
        __syncthreads();

        const uint32_t base = sT0 + (kt % 3) * ASTG_B;
        const int k0 = kt * 32;

        // ---- S = Q K^T (128x32) ----
        float s[4][4];
#pragma unroll
        for (int na = 0; na < 4; na++)
#pragma unroll
            for (int j = 0; j < 4; j++) s[na][j] = 0.f;

#pragma unroll
        for (int ks = 0; ks < 4; ks++) {
            const uint32_t qo = (uint32_t)((w * 16 + arow) * PITCHQ) + ks * 32 + akb;
            uint32_t qh[4], ql[4], kh[2][4], kl[2][4];
            ldsm_x4(qh[0], qh[1], qh[2], qh[3], sQh + qo);
            ldsm_x4(ql[0], ql[1], ql[2], ql[3], sQl + qo);
#pragma unroll
            for (int pb = 0; pb < 2; pb++) {
                uint32_t bo = (uint32_t)((pb * 16 + brow) * PITCHQ) + ks * 32 + bkb;
                ldsm_x4(kh[pb][0], kh[pb][1], kh[pb][2], kh[pb][3], base + bo);
                ldsm_x4(kl[pb][0], kl[pb][1], kl[pb][2], kl[pb][3], base + KT_B + bo);
            }
#pragma unroll
            for (int na = 0; na < 4; na++)
                mma16816(s[na], qh, kh[na >> 1][(na & 1) * 2], kh[na >> 1][(na & 1) * 2 + 1]);
#pragma unroll
            for (int na = 0; na < 4; na++)
                mma16816(s[na], ql, kh[na >> 1][(na & 1) * 2], kh[na >> 1][(na & 1) * 2 + 1]);
#pragma unroll
            for (int na = 0; na < 4; na++)
                mma16816(s[na], qh, kl[na >> 1][(na & 1) * 2], kl[na >> 1][(na & 1) * 2 + 1]);
        }

        // ---- causal mask ----
        const int r0 = q0 + w * 16 + gid, r1 = r0 + 8;
        if (k0 + 31 > r0) {
#pragma unroll
            for (int na = 0; na < 4; na++) {
                int c0 = k0 + na * 8 + tig * 2, c1 = c0 + 1;
                if (c0 > r0) s[na][0] = -1e30f;
                if (c1 > r0) s[na][1] = -1e30f;
                if (c0 > r1) s[na][2] = -1e30f;
                if (c1 > r1) s[na][3] = -1e30f;
            }
        }

        // ---- online softmax (base 2) ----
        float mx0 = -1e30f, mx1 = -1e30f;
#pragma unroll
        for (int na = 0; na < 4; na++) {
            mx0 = fmaxf(mx0, fmaxf(s[na][0], s[na][1]));
            mx1 = fmaxf(mx1, fmaxf(s[na][2], s[na][3]));
        }
        mx0 = fmaxf(mx0, __shfl_xor_sync(0xffffffffu, mx0, 1));
        mx0 = fmaxf(mx0, __shfl_xor_sync(0xffffffffu, mx0, 2));
        mx1 = fmaxf(mx1, __shfl_xor_sync(0xffffffffu, mx1, 1));
        mx1 = fmaxf(mx1, __shfl_xor_sync(0xffffffffu, mx1, 2));
        float mn0 = fmaxf(m0r, mx0), mn1 = fmaxf(m1r, mx1);
        float c0f = exp2f(m0r - mn0), c1f = exp2f(m1r - mn1);
        m0r = mn0; m1r = mn1;

        float rs0 = 0.f, rs1 = 0.f;
        uint32_t ph[4], ph2[4], pl[4], pl2[4];
#pragma unroll
        for (int na = 0; na < 4; na++) {
            float p0 = exp2f(s[na][0] - mn0);
            float p1 = exp2f(s[na][1] - mn0);
            float p2 = exp2f(s[na][2] - mn1);
            float p3 = exp2f(s[na][3] - mn1);
            rs0 += p0 + p1; rs1 += p2 + p3;
            __nv_bfloat16 h0 = __float2bfloat16(p0), h1 = __float2bfloat16(p1);
            __nv_bfloat16 h2 = __float2bfloat16(p2), h3 = __float2bfloat16(p3);
            ph[na]  = ((uint32_t)__bfloat16_as_ushort(h1) << 16) | __bfloat16_as_ushort(h0);
            ph2[na] = ((uint32_t)__bfloat16_as_ushort(h3) << 16) | __bfloat16_as_ushort(h2);
            pl[na]  = packbf2(p0 - __bfloat162float(h0), p1 - __bfloat162float(h1));
            pl2[na] = packbf2(p2 - __bfloat162float(h2), p3 - __bfloat162float(h3));
        }
        rs0 += __shfl_xor_sync(0xffffffffu, rs0, 1);
        rs0 += __shfl_xor_sync(0xffffffffu, rs0, 2);
        rs1 += __shfl_xor_sync(0xffffffffu, rs1, 1);
        rs1 += __shfl_xor_sync(0xffffffffu, rs1, 2);
        l0r = l0r * c0f + rs0;
        l1r = l1r * c1f + rs1;
#pragma unroll
        for (int na = 0; na < 8; na++) {
            accO[na][0] *= c0f; accO[na][1] *= c0f;
            accO[na][2] *= c1f; accO[na][3] *= c1f;
        }

        // ---- O += P V  (P[128x32] x V[32x64]) ----
        const uint32_t vb = base + 2 * KT_B;
#pragma unroll
        for (int ks = 0; ks < 2; ks++) {
            uint32_t vh[4][4], vl[4][4];
#pragma unroll
            for (int pb = 0; pb < 4; pb++) {
                uint32_t bo = (uint32_t)((pb * 16 + brow) * 80) + ks * 32 + bkb;
                ldsm_x4(vh[pb][0], vh[pb][1], vh[pb][2], vh[pb][3], vb + bo);
                ldsm_x4(vl[pb][0], vl[pb][1], vl[pb][2], vl[pb][3], vb + VT_B + bo);
            }
            uint32_t a_h[4] = {ph[2 * ks], ph2[2 * ks], ph[2 * ks + 1], ph2[2 * ks + 1]};
            uint32_t a_l[4] = {pl[2 * ks], pl2[2 * ks], pl[2 * ks + 1], pl2[2 * ks + 1]};
#pragma unroll
            for (int na = 0; na < 8; na++)
                mma16816(accO[na], a_h, vh[na >> 1][(na & 1) * 2],
                                        vh[na >> 1][(na & 1) * 2 + 1]);
#pragma unroll
            for (int na = 0; na < 8; na++)
                mma16816(accO[na], a_l, vh[na >> 1][(na & 1) * 2],
                                        vh[na >> 1][(na & 1) * 2 + 1]);
#pragma unroll
            for (int na = 0; na < 8; na++)
                mma16816(accO[na], a_h, vl[na >> 1][(na & 1) * 2],
                                        vl[na >> 1][(na & 1) * 2 + 1]);
        }

        if (kt + 3 < n_kv) {
            __syncthreads();      // ring slot (kt%3) free across all warps
            loadKV(kt + 3);
        }
    }

    // ---- epilogue ----
    const int b = bh >> 4, hh = bh & 15;
    const float inv0 = 1.0f / l0r, inv1 = 1.0f / l1r;
    const int r0 = q0 + w * 16 + gid, r1 = r0 + 8;
#pragma unroll
    for (int na = 0; na < 8; na++) {
        const int col = hh * 64 + na * 8 + tig * 2;
        float2 o0 = make_float2(accO[na][0] * inv0, accO[na][1] * inv0);
        float2 o1 = make_float2(accO[na][2] * inv1, accO[na][3] * inv1);
        *(float2*)&out[((size_t)(b * Tt + r0)) * Dm + col] = o0;
        *(float2*)&out[((size_t)(b * Tt + r1)) * Dm + col] = o1;
    }
}

// ---------------------------------------------------------------------------
extern "C" void kernel_launch(void* const* d_in, const int* in_sizes, int n_in,
                              void* d_out, int out_size)
{
    (void)in_sizes; (void)n_in; (void)out_size;
    const float* x  = (const float*)d_in[0];
    const float* Wq = (const float*)d_in[1];
    const float* bq = (const float*)d_in[2];
    const float* Wk = (const float*)d_in[3];
    const float* bk = (const float*)d_in[4];
    const float* Wv = (const float*)d_in[5];
    const float* bv = (const float*)d_in[6];
    float* out = (float*)d_out;

    const int nblk = (NX4 + 3 * NW4) / 256;     // 11264
    split_all<<<nblk, 256>>>(x, Wq, Wk, Wv);

    cudaFuncSetAttribute(proj_mma_kernel,
                         cudaFuncAttributeMaxDynamicSharedMemorySize, GEMM_SMEM);
    dim3 pg(Mtot / 128, Dm / 128, 3);
    proj_mma_kernel<<<pg, 256, GEMM_SMEM>>>(bq, bk, bv);

    cudaFuncSetAttribute(attn_mma_kernel,
                         cudaFuncAttributeMaxDynamicSharedMemorySize, ATTN_SMEM);
    attn_mma_kernel<<<dim3(16, 64), 256, ATTN_SMEM>>>(out);
}

// round 6
// speedup vs baseline: 2.9291x; 1.0035x over previous
#include <cuda_runtime.h>
#include <cuda_bf16.h>
#include <cstdint>

#define Dm   1024
#define Hn   16
#define HD   64
#define Bb   4
#define Tt   2048
#define BH   (Bb*Hn)
#define Mtot (Bb*Tt)
#define NX4  (Mtot*Dm/4)
#define NW4  (Dm*Dm/4)

// Split-bf16 GEMM operands
__device__ __nv_bfloat16 g_Xh[(size_t)Mtot * Dm];
__device__ __nv_bfloat16 g_Xl[(size_t)Mtot * Dm];
__device__ __nv_bfloat16 g_Wh[(size_t)3 * Dm * Dm];
__device__ __nv_bfloat16 g_Wl[(size_t)3 * Dm * Dm];
// Projection outputs, split bf16. Q pre-scaled by 8*log2(e). V^T [bh][d][t].
__device__ __nv_bfloat16 g_Qh[(size_t)BH * Tt * HD];
__device__ __nv_bfloat16 g_Ql[(size_t)BH * Tt * HD];
__device__ __nv_bfloat16 g_Kh[(size_t)BH * Tt * HD];
__device__ __nv_bfloat16 g_Kl[(size_t)BH * Tt * HD];
__device__ __nv_bfloat16 g_VtH[(size_t)BH * HD * Tt];
__device__ __nv_bfloat16 g_VtL[(size_t)BH * HD * Tt];

// ---------------------------------------------------------------------------
__device__ __forceinline__ uint32_t smem_u32(const void* p) {
    uint32_t a;
    asm("{ .reg .u64 t; cvta.to.shared.u64 t, %1; cvt.u32.u64 %0, t; }"
        : "=r"(a) : "l"(p));
    return a;
}
__device__ __forceinline__ void cpa16(uint32_t s, const void* g) {
    asm volatile("cp.async.cg.shared.global [%0], [%1], 16;" :: "r"(s), "l"(g));
}
#define CP_COMMIT() asm volatile("cp.async.commit_group;" ::: "memory")
#define CP_WAIT(n)  asm volatile("cp.async.wait_group %0;" :: "n"(n) : "memory")

__device__ __forceinline__ void ldsm_x4(uint32_t& r0, uint32_t& r1,
                                        uint32_t& r2, uint32_t& r3, uint32_t a) {
    asm volatile("ldmatrix.sync.aligned.m8n8.x4.shared.b16 {%0,%1,%2,%3}, [%4];"
                 : "=r"(r0), "=r"(r1), "=r"(r2), "=r"(r3) : "r"(a));
}
__device__ __forceinline__ void mma16816(float* c, const uint32_t* a,
                                         uint32_t b0, uint32_t b1) {
    asm volatile(
        "mma.sync.aligned.m16n8k16.row.col.f32.bf16.bf16.f32 "
        "{%0,%1,%2,%3}, {%4,%5,%6,%7}, {%8,%9}, {%0,%1,%2,%3};"
        : "+f"(c[0]), "+f"(c[1]), "+f"(c[2]), "+f"(c[3])
        : "r"(a[0]), "r"(a[1]), "r"(a[2]), "r"(a[3]), "r"(b0), "r"(b1));
}
__device__ __forceinline__ uint32_t packbf2(float a, float b) {
    uint32_t r;
    asm("cvt.rn.bf16x2.f32 %0, %1, %2;" : "=r"(r) : "f"(b), "f"(a));
    return r;
}

// ---------------------------------------------------------------------------
// Merged split: X, Wq, Wk, Wv -> (hi, lo) bf16 in one launch
// ---------------------------------------------------------------------------
__global__ __launch_bounds__(256) void split_all(
    const float* __restrict__ x, const float* __restrict__ wq,
    const float* __restrict__ wk, const float* __restrict__ wv)
{
    int i = blockIdx.x * 256 + threadIdx.x;
    const float4* src;
    ushort4 *hi, *lo;
    if (i < NX4) {
        src = (const float4*)x + i;
        hi = (ushort4*)g_Xh + i;
        lo = (ushort4*)g_Xl + i;
    } else {
        int j = i - NX4;
        int w = j >> 18;                 // NW4 = 2^18
        int o = j & (NW4 - 1);
        const float* ws = (w == 0) ? wq : (w == 1) ? wk : wv;
        src = (const float4*)ws + o;
        hi = (ushort4*)(g_Wh + (size_t)w * Dm * Dm) + o;
        lo = (ushort4*)(g_Wl + (size_t)w * Dm * Dm) + o;
    }
    float4 v = *src;
    float f[4] = {v.x, v.y, v.z, v.w};
    unsigned short h[4], l[4];
#pragma unroll
    for (int j = 0; j < 4; j++) {
        __nv_bfloat16 hb = __float2bfloat16(f[j]);
        __nv_bfloat16 lb = __float2bfloat16(f[j] - __bfloat162float(hb));
        h[j] = __bfloat16_as_ushort(hb);
        l[j] = __bfloat16_as_ushort(lb);
    }
    *hi = make_ushort4(h[0], h[1], h[2], h[3]);
    *lo = make_ushort4(l[0], l[1], l[2], l[3]);
}

// ---------------------------------------------------------------------------
// Projection GEMM (HMMA split-bf16). 128x128 tile, BK=32, 2-stage cp.async,
// 2 CTAs/SM. Staged fragment loads keep regs under the 128 cap.
// ---------------------------------------------------------------------------
#define BKp      32
#define NSTp     (Dm / BKp)         // 32
#define PITCH_P  80
#define TILE_P   (128 * PITCH_P)    // 10240
#define STG_P    (4 * TILE_P)       // 40960
#define GEMM_SMEM (2 * STG_P)       // 81920

__global__ __launch_bounds__(256, 2) void proj_mma_kernel(
    const float* __restrict__ bq, const float* __restrict__ bk,
    const float* __restrict__ bv)
{
    extern __shared__ char smem[];
    const int tid  = threadIdx.x;
    const int z    = blockIdx.z;
    const int m0   = blockIdx.x * 128;
    const int n0   = blockIdx.y * 128;

    const uint4* Xh4 = (const uint4*)g_Xh;
    const uint4* Xl4 = (const uint4*)g_Xl;
    const uint4* Wh4 = (const uint4*)(g_Wh + (size_t)z * Dm * Dm);
    const uint4* Wl4 = (const uint4*)(g_Wl + (size_t)z * Dm * Dm);
    const float* bias = (z == 0) ? bq : (z == 1) ? bk : bv;
    __nv_bfloat16* OutH = (z == 0) ? g_Qh : g_Kh;
    __nv_bfloat16* OutL = (z == 0) ? g_Ql : g_Kl;

    const uint32_t sb = smem_u32(smem);
    const int warp = tid >> 5, lane = tid & 31;
    const int wm = warp >> 2;
    const int wn = warp & 3;
    const int a_row = wm * 64 + (lane & 7) + ((lane >> 3) & 1) * 8;
    const uint32_t a_kb = ((lane >> 4) & 1) * 16;
    const int b_row = wn * 32 + (lane & 7) + ((lane >> 4) & 1) * 8;
    const uint32_t b_kb = ((lane >> 3) & 1) * 16;

    float acc[4][4][4];
#pragma unroll
    for (int i = 0; i < 4; i++)
#pragma unroll
        for (int j = 0; j < 4; j++)
#pragma unroll
            for (int k = 0; k < 4; k++) acc[i][j][k] = 0.f;

    // stage loads: each array 128 rows x 4 segs(16B) = 512 cp.async
    auto issue_stage = [&](int s) {
        const uint32_t base = sb + (s & 1) * STG_P;
        const int kseg0 = s * (BKp / 8);
#pragma unroll
        for (int j = 0; j < 2; j++) {
            int idx = tid + 256 * j;
            int row = idx >> 2, seg = idx & 3;
            uint32_t so = (uint32_t)(row * PITCH_P + seg * 16);
            size_t ga = (size_t)(m0 + row) * 128 + kseg0 + seg;
            size_t gb = (size_t)(n0 + row) * 128 + kseg0 + seg;
            cpa16(base + so,              Xh4 + ga);
            cpa16(base + TILE_P + so,     Xl4 + ga);
            cpa16(base + 2 * TILE_P + so, Wh4 + gb);
            cpa16(base + 3 * TILE_P + so, Wl4 + gb);
        }
        CP_COMMIT();
    };

    issue_stage(0);

    for (int s = 0; s < NSTp; s++) {
        if (s + 1 < NSTp) { issue_stage(s + 1); CP_WAIT(1); }
        else              { CP_WAIT(0); }
        __syncthreads();

        const uint32_t base = sb + (s & 1) * STG_P;
        const uint32_t Ah = base, Al = base + TILE_P;
        const uint32_t Bh = base + 2 * TILE_P, Bl = base + 3 * TILE_P;

#pragma unroll
        for (int ks = 0; ks < 2; ks++) {
            const uint32_t ko = ks * 32;
            uint32_t af[4][4], tf[4][4], bf[2][4];
#pragma unroll
            for (int ma = 0; ma < 4; ma++) {
                uint32_t ao = (uint32_t)((a_row + ma * 16) * PITCH_P) + ko + a_kb;
                ldsm_x4(af[ma][0], af[ma][1], af[ma][2], af[ma][3], Ah + ao);
            }
#pragma unroll
            for (int pb = 0; pb < 2; pb++) {
                uint32_t bo = (uint32_t)((b_row + pb * 16) * PITCH_P) + ko + b_kb;
                ldsm_x4(bf[pb][0], bf[pb][1], bf[pb][2], bf[pb][3], Bh + bo);
            }
#pragma unroll
            for (int ma = 0; ma < 4; ma++)
#pragma unroll
                for (int na = 0; na < 4; na++)
                    mma16816(acc[ma][na], af[ma],
                             bf[na >> 1][(na & 1) * 2], bf[na >> 1][(na & 1) * 2 + 1]);
            // lo(A) x hi(B)
#pragma unroll
            for (int ma = 0; ma < 4; ma++) {
                uint32_t ao = (uint32_t)((a_row + ma * 16) * PITCH_P) + ko + a_kb;
                ldsm_x4(tf[ma][0], tf[ma][1], tf[ma][2], tf[ma][3], Al + ao);
            }
#pragma unroll
            for (int ma = 0; ma < 4; ma++)
#pragma unroll
                for (int na = 0; na < 4; na++)
                    mma16816(acc[ma][na], tf[ma],
                             bf[na >> 1][(na & 1) * 2], bf[na >> 1][(na & 1) * 2 + 1]);
            // hi(A) x lo(B) — overwrite bf
#pragma unroll
            for (int pb = 0; pb < 2; pb++) {
                uint32_t bo = (uint32_t)((b_row + pb * 16) * PITCH_P) + ko + b_kb;
                ldsm_x4(bf[pb][0], bf[pb][1], bf[pb][2], bf[pb][3], Bl + bo);
            }
#pragma unroll
            for (int ma = 0; ma < 4; ma++)
#pragma unroll
                for (int na = 0; na < 4; na++)
                    mma16816(acc[ma][na], af[ma],
                             bf[na >> 1][(na & 1) * 2], bf[na >> 1][(na & 1) * 2 + 1]);
        }
        __syncthreads();
    }

    // epilogue: +bias, (Q: x 8*log2e), split to bf16 hi/lo
    const int gid = lane >> 2, tig = lane & 3;
    const float qscale = (z == 0) ? 11.541560327111707f : 1.0f;   // 8*log2(e)
#pragma unroll
    for (int ma = 0; ma < 4; ma++) {
#pragma unroll
        for (int na = 0; na < 4; na++) {
            const int col = n0 + wn * 32 + na * 8 + tig * 2;
            const float2 bv2 = *(const float2*)&bias[col];
            const int hh = col >> 6, d = col & 63;
#pragma unroll
            for (int half = 0; half < 2; half++) {
                const int row = m0 + wm * 64 + ma * 16 + gid + half * 8;
                const int b = row >> 11, t = row & 2047;
                const int bhidx = (b << 4) + hh;
                float v0 = (acc[ma][na][half * 2 + 0] + bv2.x) * qscale;
                float v1 = (acc[ma][na][half * 2 + 1] + bv2.y) * qscale;
                __nv_bfloat16 h0 = __float2bfloat16(v0);
                __nv_bfloat16 h1 = __float2bfloat16(v1);
                __nv_bfloat16 l0 = __float2bfloat16(v0 - __bfloat162float(h0));
                __nv_bfloat16 l1 = __float2bfloat16(v1 - __bfloat162float(h1));
                if (z < 2) {
                    size_t ix = ((size_t)bhidx * Tt + t) * HD + d;
                    uint32_t ph = ((uint32_t)__bfloat16_as_ushort(h1) << 16) |
                                   __bfloat16_as_ushort(h0);
                    uint32_t pl = ((uint32_t)__bfloat16_as_ushort(l1) << 16) |
                                   __bfloat16_as_ushort(l0);
                    *(uint32_t*)&OutH[ix] = ph;
                    *(uint32_t*)&OutL[ix] = pl;
                } else {
                    size_t ix = ((size_t)bhidx * HD + d) * Tt + t;
                    g_VtH[ix]      = h0;  g_VtH[ix + Tt] = h1;
                    g_VtL[ix]      = l0;  g_VtL[ix + Tt] = l1;
                }
            }
        }
    }
}

// ---------------------------------------------------------------------------
// Flash attention, HMMA split-bf16, base-2 softmax (Q pre-scaled 8*log2e).
// BQ=128 (8 warps x M16), BKV=32, 3-stage cp.async ring, 2 CTAs/SM.
// ---------------------------------------------------------------------------
#define PITCHQ  144
#define AQ_B    (128 * PITCHQ)        // 18432 per Q array
#define KT_B    (32 * PITCHQ)         // 4608 per K array (32 t-rows x 64 d)
#define VT_B    (64 * 80)             // 5120 per V array (64 d-rows x 32 t)
#define ASTG_B  (2 * KT_B + 2 * VT_B) // 19456
#define ATTN_SMEM (2 * AQ_B + 3 * ASTG_B)   // 95232

__global__ __launch_bounds__(256, 2) void attn_mma_kernel(float* __restrict__ out)
{
    extern __shared__ char smem[];
    const int tid  = threadIdx.x;
    const int w    = tid >> 5, lane = tid & 31;
    const int qi   = (int)gridDim.x - 1 - (int)blockIdx.x;   // long CTAs first
    const int bh   = blockIdx.y;
    const int q0   = qi * 128;
    const int n_kv = 4 * (qi + 1);

    const uint32_t sb  = smem_u32(smem);
    const uint32_t sQh = sb, sQl = sb + AQ_B;
    const uint32_t sT0 = sb + 2 * AQ_B;

    const int gid = lane >> 2, tig = lane & 3;
    const int arow = (lane & 7) + ((lane >> 3) & 1) * 8;
    const uint32_t akb = ((lane >> 4) & 1) * 16;
    const int brow = (lane & 7) + ((lane >> 4) & 1) * 8;
    const uint32_t bkb = ((lane >> 3) & 1) * 16;

    // Q: 128 rows x 64 bf16 (hi+lo) — part of commit group 0
#pragma unroll
    for (int j = 0; j < 4; j++) {
        int idx = tid + 256 * j;
        int row = idx >> 3, seg = idx & 7;
        uint32_t so = (uint32_t)(row * PITCHQ + seg * 16);
        size_t g = ((size_t)bh * Tt + q0 + row) * HD + seg * 8;
        cpa16(sQh + so, g_Qh + g);
        cpa16(sQl + so, g_Ql + g);
    }
    auto loadKV = [&](int kt) {
        const uint32_t base = sT0 + (kt % 3) * ASTG_B;
        const int k0 = kt * 32;
        {   // K: 32 rows(t) x 8 segs
            int row = tid >> 3, seg = tid & 7;
            if (tid < 256) {
                uint32_t so = (uint32_t)(row * PITCHQ + seg * 16);
                size_t gk = ((size_t)bh * Tt + k0 + row) * HD + seg * 8;
                cpa16(base + so,        g_Kh + gk);
                cpa16(base + KT_B + so, g_Kl + gk);
            }
        }
        {   // V^T: 64 rows(d) x 4 segs
            int row = tid >> 2, seg = tid & 3;
            uint32_t so = (uint32_t)(row * 80 + seg * 16);
            size_t gv = ((size_t)bh * HD + row) * Tt + k0 + seg * 8;
            cpa16(base + 2 * KT_B + so,        g_VtH + gv);
            cpa16(base + 2 * KT_B + VT_B + so, g_VtL + gv);
        }
        CP_COMMIT();
    };

    loadKV(0);
    loadKV(1);
    loadKV(2);

    float m0r = -1e30f, m1r = -1e30f, l0r = 0.f, l1r = 0.f;
    float accO[8][4];
#pragma unroll
    for (int na = 0; na < 8; na++)
#pragma unroll
        for (int j = 0; j < 4; j++) accO[na][j] = 0.f;

    for (int kt = 0; kt < n_kv; kt++) {
        if (kt + 2 < n_kv)      { CP_WAIT(2); }
        else if (kt + 1 < n_kv) { CP_WAIT(1); }
        else                    { CP_WAIT(0); }
        __syncthreads();

        const uint32_t base = sT0 + (kt % 3) * ASTG_B;
        const int k0 = kt * 32;

        // ---- S = Q K^T (128x32) ----
        float s[4][4];
#pragma unroll
        for (int na = 0; na < 4; na++)
#pragma unroll
            for (int j = 0; j < 4; j++) s[na][j] = 0.f;

#pragma unroll
        for (int ks = 0; ks < 4; ks++) {
            const uint32_t qo = (uint32_t)((w * 16 + arow) * PITCHQ) + ks * 32 + akb;
            uint32_t qh[4], ql[4], kh[2][4], kl[2][4];
            ldsm_x4(qh[0], qh[1], qh[2], qh[3], sQh + qo);
            ldsm_x4(ql[0], ql[1], ql[2], ql[3], sQl + qo);
#pragma unroll
            for (int pb = 0; pb < 2; pb++) {
                uint32_t bo = (uint32_t)((pb * 16 + brow) * PITCHQ) + ks * 32 + bkb;
                ldsm_x4(kh[pb][0], kh[pb][1], kh[pb][2], kh[pb][3], base + bo);
                ldsm_x4(kl[pb][0], kl[pb][1], kl[pb][2], kl[pb][3], base + KT_B + bo);
            }
#pragma unroll
            for (int na = 0; na < 4; na++)
                mma16816(s[na], qh, kh[na >> 1][(na & 1) * 2], kh[na >> 1][(na & 1) * 2 + 1]);
#pragma unroll
            for (int na = 0; na < 4; na++)
                mma16816(s[na], ql, kh[na >> 1][(na & 1) * 2], kh[na >> 1][(na & 1) * 2 + 1]);
#pragma unroll
            for (int na = 0; na < 4; na++)
                mma16816(s[na], qh, kl[na >> 1][(na & 1) * 2], kl[na >> 1][(na & 1) * 2 + 1]);
        }

        // ---- causal mask ----
        const int r0 = q0 + w * 16 + gid, r1 = r0 + 8;
        if (k0 + 31 > r0) {
#pragma unroll
            for (int na = 0; na < 4; na++) {
                int c0 = k0 + na * 8 + tig * 2, c1 = c0 + 1;
                if (c0 > r0) s[na][0] = -1e30f;
                if (c1 > r0) s[na][1] = -1e30f;
                if (c0 > r1) s[na][2] = -1e30f;
                if (c1 > r1) s[na][3] = -1e30f;
            }
        }

        // ---- online softmax (base 2) ----
        float mx0 = -1e30f, mx1 = -1e30f;
#pragma unroll
        for (int na = 0; na < 4; na++) {
            mx0 = fmaxf(mx0, fmaxf(s[na][0], s[na][1]));
            mx1 = fmaxf(mx1, fmaxf(s[na][2], s[na][3]));
        }
        mx0 = fmaxf(mx0, __shfl_xor_sync(0xffffffffu, mx0, 1));
        mx0 = fmaxf(mx0, __shfl_xor_sync(0xffffffffu, mx0, 2));
        mx1 = fmaxf(mx1, __shfl_xor_sync(0xffffffffu, mx1, 1));
        mx1 = fmaxf(mx1, __shfl_xor_sync(0xffffffffu, mx1, 2));
        float mn0 = fmaxf(m0r, mx0), mn1 = fmaxf(m1r, mx1);
        float c0f = exp2f(m0r - mn0), c1f = exp2f(m1r - mn1);
        m0r = mn0; m1r = mn1;

        float rs0 = 0.f, rs1 = 0.f;
        uint32_t ph[4], ph2[4], pl[4], pl2[4];
#pragma unroll
        for (int na = 0; na < 4; na++) {
            float p0 = exp2f(s[na][0] - mn0);
            float p1 = exp2f(s[na][1] - mn0);
            float p2 = exp2f(s[na][2] - mn1);
            float p3 = exp2f(s[na][3] - mn1);
            rs0 += p0 + p1; rs1 += p2 + p3;
            __nv_bfloat16 h0 = __float2bfloat16(p0), h1 = __float2bfloat16(p1);
            __nv_bfloat16 h2 = __float2bfloat16(p2), h3 = __float2bfloat16(p3);
            ph[na]  = ((uint32_t)__bfloat16_as_ushort(h1) << 16) | __bfloat16_as_ushort(h0);
            ph2[na] = ((uint32_t)__bfloat16_as_ushort(h3) << 16) | __bfloat16_as_ushort(h2);
            pl[na]  = packbf2(p0 - __bfloat162float(h0), p1 - __bfloat162float(h1));
            pl2[na] = packbf2(p2 - __bfloat162float(h2), p3 - __bfloat162float(h3));
        }
        rs0 += __shfl_xor_sync(0xffffffffu, rs0, 1);
        rs0 += __shfl_xor_sync(0xffffffffu, rs0, 2);
        rs1 += __shfl_xor_sync(0xffffffffu, rs1, 1);
        rs1 += __shfl_xor_sync(0xffffffffu, rs1, 2);
        l0r = l0r * c0f + rs0;
        l1r = l1r * c1f + rs1;
#pragma unroll
        for (int na = 0; na < 8; na++) {
            accO[na][0] *= c0f; accO[na][1] *= c0f;
            accO[na][2] *= c1f; accO[na][3] *= c1f;
        }

        // ---- O += P V  (P[128x32] x V[32x64]) ----
        const uint32_t vb = base + 2 * KT_B;
#pragma unroll
        for (int ks = 0; ks < 2; ks++) {
            uint32_t vh[4][4], vl[4][4];
#pragma unroll
            for (int pb = 0; pb < 4; pb++) {
                uint32_t bo = (uint32_t)((pb * 16 + brow) * 80) + ks * 32 + bkb;
                ldsm_x4(vh[pb][0], vh[pb][1], vh[pb][2], vh[pb][3], vb + bo);
                ldsm_x4(vl[pb][0], vl[pb][1], vl[pb][2], vl[pb][3], vb + VT_B + bo);
            }
            uint32_t a_h[4] = {ph[2 * ks], ph2[2 * ks], ph[2 * ks + 1], ph2[2 * ks + 1]};
            uint32_t a_l[4] = {pl[2 * ks], pl2[2 * ks], pl[2 * ks + 1], pl2[2 * ks + 1]};
#pragma unroll
            for (int na = 0; na < 8; na++)
                mma16816(accO[na], a_h, vh[na >> 1][(na & 1) * 2],
                                        vh[na >> 1][(na & 1) * 2 + 1]);
#pragma unroll
            for (int na = 0; na < 8; na++)
                mma16816(accO[na], a_l, vh[na >> 1][(na & 1) * 2],
                                        vh[na >> 1][(na & 1) * 2 + 1]);
#pragma unroll
            for (int na = 0; na < 8; na++)
                mma16816(accO[na], a_h, vl[na >> 1][(na & 1) * 2],
                                        vl[na >> 1][(na & 1) * 2 + 1]);
        }

        if (kt + 3 < n_kv) {
            __syncthreads();      // ring slot (kt%3) free across all warps
            loadKV(kt + 3);
        }
    }

    // ---- epilogue ----
    const int b = bh >> 4, hh = bh & 15;
    const float inv0 = 1.0f / l0r, inv1 = 1.0f / l1r;
    const int r0 = q0 + w * 16 + gid, r1 = r0 + 8;
#pragma unroll
    for (int na = 0; na < 8; na++) {
        const int col = hh * 64 + na * 8 + tig * 2;
        float2 o0 = make_float2(accO[na][0] * inv0, accO[na][1] * inv0);
        float2 o1 = make_float2(accO[na][2] * inv1, accO[na][3] * inv1);
        *(float2*)&out[((size_t)(b * Tt + r0)) * Dm + col] = o0;
        *(float2*)&out[((size_t)(b * Tt + r1)) * Dm + col] = o1;
    }
}

// ---------------------------------------------------------------------------
extern "C" void kernel_launch(void* const* d_in, const int* in_sizes, int n_in,
                              void* d_out, int out_size)
{
    (void)in_sizes; (void)n_in; (void)out_size;
    const float* x  = (const float*)d_in[0];
    const float* Wq = (const float*)d_in[1];
    const float* bq = (const float*)d_in[2];
    const float* Wk = (const float*)d_in[3];
    const float* bk = (const float*)d_in[4];
    const float* Wv = (const float*)d_in[5];
    const float* bv = (const float*)d_in[6];
    float* out = (float*)d_out;

    const int nblk = (NX4 + 3 * NW4) / 256;     // 11264
    split_all<<<nblk, 256>>>(x, Wq, Wk, Wv);

    cudaFuncSetAttribute(proj_mma_kernel,
                         cudaFuncAttributeMaxDynamicSharedMemorySize, GEMM_SMEM);
    dim3 pg(Mtot / 128, Dm / 128, 3);
    proj_mma_kernel<<<pg, 256, GEMM_SMEM>>>(bq, bk, bv);

    cudaFuncSetAttribute(attn_mma_kernel,
                         cudaFuncAttributeMaxDynamicSharedMemorySize, ATTN_SMEM);
    attn_mma_kernel<<<dim3(16, 64), 256, ATTN_SMEM>>>(out);
}

// round 7
// speedup vs baseline: 2.9812x; 1.0178x over previous
#include <cuda_runtime.h>
#include <cuda_fp16.h>
#include <cstdint>

#define Dm   1024
#define Hn   16
#define HD   64
#define Bb   4
#define Tt   2048
#define BH   (Bb*Hn)
#define Mtot (Bb*Tt)
#define NX4  (Mtot*Dm/4)
#define NW4  (Dm*Dm/4)

// Split-fp16 GEMM operands
__device__ __half g_Xh[(size_t)Mtot * Dm];
__device__ __half g_Xl[(size_t)Mtot * Dm];
__device__ __half g_Wh[(size_t)3 * Dm * Dm];
__device__ __half g_Wl[(size_t)3 * Dm * Dm];
// Projection outputs. Q pre-scaled by 8*log2(e). Q/K split fp16; V^T single fp16.
__device__ __half g_Qh[(size_t)BH * Tt * HD];
__device__ __half g_Ql[(size_t)BH * Tt * HD];
__device__ __half g_Kh[(size_t)BH * Tt * HD];
__device__ __half g_Kl[(size_t)BH * Tt * HD];
__device__ __half g_Vt[(size_t)BH * HD * Tt];

// ---------------------------------------------------------------------------
__device__ __forceinline__ uint32_t smem_u32(const void* p) {
    uint32_t a;
    asm("{ .reg .u64 t; cvta.to.shared.u64 t, %1; cvt.u32.u64 %0, t; }"
        : "=r"(a) : "l"(p));
    return a;
}
__device__ __forceinline__ void cpa16(uint32_t s, const void* g) {
    asm volatile("cp.async.cg.shared.global [%0], [%1], 16;" :: "r"(s), "l"(g));
}
#define CP_COMMIT() asm volatile("cp.async.commit_group;" ::: "memory")
#define CP_WAIT(n)  asm volatile("cp.async.wait_group %0;" :: "n"(n) : "memory")

__device__ __forceinline__ void ldsm_x4(uint32_t& r0, uint32_t& r1,
                                        uint32_t& r2, uint32_t& r3, uint32_t a) {
    asm volatile("ldmatrix.sync.aligned.m8n8.x4.shared.b16 {%0,%1,%2,%3}, [%4];"
                 : "=r"(r0), "=r"(r1), "=r"(r2), "=r"(r3) : "r"(a));
}
// fp16 x fp16 -> fp32 accumulate
__device__ __forceinline__ void mma_ff32(float* c, const uint32_t* a,
                                         uint32_t b0, uint32_t b1) {
    asm volatile(
        "mma.sync.aligned.m16n8k16.row.col.f32.f16.f16.f32 "
        "{%0,%1,%2,%3}, {%4,%5,%6,%7}, {%8,%9}, {%0,%1,%2,%3};"
        : "+f"(c[0]), "+f"(c[1]), "+f"(c[2]), "+f"(c[3])
        : "r"(a[0]), "r"(a[1]), "r"(a[2]), "r"(a[3]), "r"(b0), "r"(b1));
}
// fp16 x fp16 -> fp16 accumulate (correction terms)
__device__ __forceinline__ void mma_ff16(uint32_t* c, const uint32_t* a,
                                         uint32_t b0, uint32_t b1) {
    asm volatile(
        "mma.sync.aligned.m16n8k16.row.col.f16.f16.f16.f16 "
        "{%0,%1}, {%2,%3,%4,%5}, {%6,%7}, {%0,%1};"
        : "+r"(c[0]), "+r"(c[1])
        : "r"(a[0]), "r"(a[1]), "r"(a[2]), "r"(a[3]), "r"(b0), "r"(b1));
}
__device__ __forceinline__ uint32_t packh2(float lo, float hi) {
    __half2 h = __floats2half2_rn(lo, hi);
    return *reinterpret_cast<uint32_t*>(&h);
}
__device__ __forceinline__ float h2lo(uint32_t u) {
    return __half2float(__ushort_as_half((unsigned short)(u & 0xffffu)));
}
__device__ __forceinline__ float h2hi(uint32_t u) {
    return __half2float(__ushort_as_half((unsigned short)(u >> 16)));
}

// ---------------------------------------------------------------------------
// Merged split: X, Wq, Wk, Wv -> (hi, lo) fp16 in one launch
// ---------------------------------------------------------------------------
__global__ __launch_bounds__(256) void split_all(
    const float* __restrict__ x, const float* __restrict__ wq,
    const float* __restrict__ wk, const float* __restrict__ wv)
{
    int i = blockIdx.x * 256 + threadIdx.x;
    const float4* src;
    ushort4 *hi, *lo;
    if (i < NX4) {
        src = (const float4*)x + i;
        hi = (ushort4*)g_Xh + i;
        lo = (ushort4*)g_Xl + i;
    } else {
        int j = i - NX4;
        int w = j >> 18;                 // NW4 = 2^18
        int o = j & (NW4 - 1);
        const float* ws = (w == 0) ? wq : (w == 1) ? wk : wv;
        src = (const float4*)ws + o;
        hi = (ushort4*)(g_Wh + (size_t)w * Dm * Dm) + o;
        lo = (ushort4*)(g_Wl + (size_t)w * Dm * Dm) + o;
    }
    float4 v = *src;
    float f[4] = {v.x, v.y, v.z, v.w};
    unsigned short h[4], l[4];
#pragma unroll
    for (int j = 0; j < 4; j++) {
        __half hb = __float2half_rn(f[j]);
        __half lb = __float2half_rn(f[j] - __half2float(hb));
        h[j] = __half_as_ushort(hb);
        l[j] = __half_as_ushort(lb);
    }
    *hi = make_ushort4(h[0], h[1], h[2], h[3]);
    *lo = make_ushort4(l[0], l[1], l[2], l[3]);
}

// ---------------------------------------------------------------------------
// Projection GEMM (HMMA split-fp16). 128x128 tile, BK=32, 2-stage cp.async.
// Main product Xh*Wh in fp32 accum; corrections Xl*Wh (+ Xh*Wl for Q/K) in
// fp16 accum. V (z==2) skips Xh*Wl and stores single-fp16 V^T.
// ---------------------------------------------------------------------------
#define BKp      32
#define NSTp     (Dm / BKp)         // 32
#define PITCH_P  80
#define TILE_P   (128 * PITCH_P)    // 10240
#define STG_P    (4 * TILE_P)       // 40960
#define GEMM_SMEM (2 * STG_P)       // 81920

__global__ __launch_bounds__(256) void proj_mma_kernel(
    const float* __restrict__ bq, const float* __restrict__ bk,
    const float* __restrict__ bv)
{
    extern __shared__ char smem[];
    const int tid  = threadIdx.x;
    const int z    = blockIdx.z;
    const int m0   = blockIdx.x * 128;
    const int n0   = blockIdx.y * 128;

    const uint4* Xh4 = (const uint4*)g_Xh;
    const uint4* Xl4 = (const uint4*)g_Xl;
    const uint4* Wh4 = (const uint4*)(g_Wh + (size_t)z * Dm * Dm);
    const uint4* Wl4 = (const uint4*)(g_Wl + (size_t)z * Dm * Dm);
    const float* bias = (z == 0) ? bq : (z == 1) ? bk : bv;
    __half* OutH = (z == 0) ? g_Qh : g_Kh;
    __half* OutL = (z == 0) ? g_Ql : g_Kl;

    const uint32_t sb = smem_u32(smem);
    const int warp = tid >> 5, lane = tid & 31;
    const int wm = warp >> 2;
    const int wn = warp & 3;
    const int a_row = wm * 64 + (lane & 7) + ((lane >> 3) & 1) * 8;
    const uint32_t a_kb = ((lane >> 4) & 1) * 16;
    const int b_row = wn * 32 + (lane & 7) + ((lane >> 4) & 1) * 8;
    const uint32_t b_kb = ((lane >> 3) & 1) * 16;

    float acc[4][4][4];
    uint32_t ch[4][4][2];
#pragma unroll
    for (int i = 0; i < 4; i++)
#pragma unroll
        for (int j = 0; j < 4; j++) {
#pragma unroll
            for (int k = 0; k < 4; k++) acc[i][j][k] = 0.f;
            ch[i][j][0] = 0u; ch[i][j][1] = 0u;
        }

    auto issue_stage = [&](int s) {
        const uint32_t base = sb + (s & 1) * STG_P;
        const int kseg0 = s * (BKp / 8);
#pragma unroll
        for (int j = 0; j < 2; j++) {
            int idx = tid + 256 * j;
            int row = idx >> 2, seg = idx & 3;
            uint32_t so = (uint32_t)(row * PITCH_P + seg * 16);
            size_t ga = (size_t)(m0 + row) * 128 + kseg0 + seg;
            size_t gb = (size_t)(n0 + row) * 128 + kseg0 + seg;
            cpa16(base + so,              Xh4 + ga);
            cpa16(base + TILE_P + so,     Xl4 + ga);
            cpa16(base + 2 * TILE_P + so, Wh4 + gb);
            cpa16(base + 3 * TILE_P + so, Wl4 + gb);
        }
        CP_COMMIT();
    };

    issue_stage(0);

    for (int s = 0; s < NSTp; s++) {
        if (s + 1 < NSTp) { issue_stage(s + 1); CP_WAIT(1); }
        else              { CP_WAIT(0); }
        __syncthreads();

        const uint32_t base = sb + (s & 1) * STG_P;
        const uint32_t Ah = base, Al = base + TILE_P;
        const uint32_t Bh = base + 2 * TILE_P, Bl = base + 3 * TILE_P;

#pragma unroll
        for (int ks = 0; ks < 2; ks++) {
            const uint32_t ko = ks * 32;
            uint32_t af[4][4], tf[4][4], bf[2][4];
#pragma unroll
            for (int ma = 0; ma < 4; ma++) {
                uint32_t ao = (uint32_t)((a_row + ma * 16) * PITCH_P) + ko + a_kb;
                ldsm_x4(af[ma][0], af[ma][1], af[ma][2], af[ma][3], Ah + ao);
            }
#pragma unroll
            for (int pb = 0; pb < 2; pb++) {
                uint32_t bo = (uint32_t)((b_row + pb * 16) * PITCH_P) + ko + b_kb;
                ldsm_x4(bf[pb][0], bf[pb][1], bf[pb][2], bf[pb][3], Bh + bo);
            }
            // main: Xh * Wh -> fp32 acc
#pragma unroll
            for (int ma = 0; ma < 4; ma++)
#pragma unroll
                for (int na = 0; na < 4; na++)
                    mma_ff32(acc[ma][na], af[ma],
                             bf[na >> 1][(na & 1) * 2], bf[na >> 1][(na & 1) * 2 + 1]);
            // corr: Xl * Wh -> fp16 acc
#pragma unroll
            for (int ma = 0; ma < 4; ma++) {
                uint32_t ao = (uint32_t)((a_row + ma * 16) * PITCH_P) + ko + a_kb;
                ldsm_x4(tf[ma][0], tf[ma][1], tf[ma][2], tf[ma][3], Al + ao);
            }
#pragma unroll
            for (int ma = 0; ma < 4; ma++)
#pragma unroll
                for (int na = 0; na < 4; na++)
                    mma_ff16(ch[ma][na], tf[ma],
                             bf[na >> 1][(na & 1) * 2], bf[na >> 1][(na & 1) * 2 + 1]);
            // corr: Xh * Wl -> fp16 acc (skip for V: its error budget allows it)
            if (z != 2) {
#pragma unroll
                for (int pb = 0; pb < 2; pb++) {
                    uint32_t bo = (uint32_t)((b_row + pb * 16) * PITCH_P) + ko + b_kb;
                    ldsm_x4(bf[pb][0], bf[pb][1], bf[pb][2], bf[pb][3], Bl + bo);
                }
#pragma unroll
                for (int ma = 0; ma < 4; ma++)
#pragma unroll
                    for (int na = 0; na < 4; na++)
                        mma_ff16(ch[ma][na], af[ma],
                                 bf[na >> 1][(na & 1) * 2], bf[na >> 1][(na & 1) * 2 + 1]);
            }
        }
        __syncthreads();
    }

    // epilogue: merge corrections, +bias, (Q: x 8*log2e), store
    const int gid = lane >> 2, tig = lane & 3;
    const float qscale = (z == 0) ? 11.541560327111707f : 1.0f;   // 8*log2(e)
#pragma unroll
    for (int ma = 0; ma < 4; ma++) {
#pragma unroll
        for (int na = 0; na < 4; na++) {
            const int col = n0 + wn * 32 + na * 8 + tig * 2;
            const float2 bv2 = *(const float2*)&bias[col];
            const int hh = col >> 6, d = col & 63;
            float c4[4];
            c4[0] = acc[ma][na][0] + h2lo(ch[ma][na][0]);
            c4[1] = acc[ma][na][1] + h2hi(ch[ma][na][0]);
            c4[2] = acc[ma][na][2] + h2lo(ch[ma][na][1]);
            c4[3] = acc[ma][na][3] + h2hi(ch[ma][na][1]);
#pragma unroll
            for (int half = 0; half < 2; half++) {
                const int row = m0 + wm * 64 + ma * 16 + gid + half * 8;
                const int t = row & 2047;
                const int bhidx = ((row >> 11) << 4) + hh;
                float v0 = (c4[half * 2 + 0] + bv2.x) * qscale;
                float v1 = (c4[half * 2 + 1] + bv2.y) * qscale;
                __half h0 = __float2half_rn(v0);
                __half h1 = __float2half_rn(v1);
                if (z < 2) {
                    __half l0 = __float2half_rn(v0 - __half2float(h0));
                    __half l1 = __float2half_rn(v1 - __half2float(h1));
                    size_t ix = ((size_t)bhidx * Tt + t) * HD + d;
                    uint32_t ph = ((uint32_t)__half_as_ushort(h1) << 16) |
                                   __half_as_ushort(h0);
                    uint32_t pl = ((uint32_t)__half_as_ushort(l1) << 16) |
                                   __half_as_ushort(l0);
                    *(uint32_t*)&OutH[ix] = ph;
                    *(uint32_t*)&OutL[ix] = pl;
                } else {
                    size_t ix = ((size_t)bhidx * HD + d) * Tt + t;
                    g_Vt[ix]      = h0;
                    g_Vt[ix + Tt] = h1;
                }
            }
        }
    }
}

// ---------------------------------------------------------------------------
// Flash attention, HMMA fp16, base-2 softmax (Q pre-scaled 8*log2e).
// S: QhKh (fp32 acc) + QlKh + QhKl (fp16 acc). PV: single product, P & V fp16.
// BQ=128 (8 warps x M16), BKV=32, 3-stage cp.async ring, 2 CTAs/SM.
// ---------------------------------------------------------------------------
#define PITCHQ  144
#define AQ_B    (128 * PITCHQ)        // 18432 per Q array
#define KT_B    (32 * PITCHQ)         // 4608 per K array
#define VT_B    (64 * 80)             // 5120 V^T (single fp16)
#define ASTG_B  (2 * KT_B + VT_B)     // 14336
#define ATTN_SMEM (2 * AQ_B + 3 * ASTG_B)   // 79872

__global__ __launch_bounds__(256, 2) void attn_mma_kernel(float* __restrict__ out)
{
    extern __shared__ char smem[];
    const int tid  = threadIdx.x;
    const int w    = tid >> 5, lane = tid & 31;
    const int qi   = (int)gridDim.x - 1 - (int)blockIdx.x;   // long CTAs first
    const int bh   = blockIdx.y;
    const int q0   = qi * 128;
    const int n_kv = 4 * (qi + 1);

    const uint32_t sb  = smem_u32(smem);
    const uint32_t sQh = sb, sQl = sb + AQ_B;
    const uint32_t sT0 = sb + 2 * AQ_B;

    const int gid = lane >> 2, tig = lane & 3;
    const int arow = (lane & 7) + ((lane >> 3) & 1) * 8;
    const uint32_t akb = ((lane >> 4) & 1) * 16;
    const int brow = (lane & 7) + ((lane >> 4) & 1) * 8;
    const uint32_t bkb = ((lane >> 3) & 1) * 16;

    // Q: 128 rows x 64 fp16 (hi+lo) — joins commit group 0
#pragma unroll
    for (int j = 0; j < 4; j++) {
        int idx = tid + 256 * j;
        int row = idx >> 3, seg = idx & 7;
        uint32_t so = (uint32_t)(row * PITCHQ + seg * 16);
        size_t g = ((size_t)bh * Tt + q0 + row) * HD + seg * 8;
        cpa16(sQh + so, g_Qh + g);
        cpa16(sQl + so, g_Ql + g);
    }
    auto loadKV = [&](int kt) {
        const uint32_t base = sT0 + (kt % 3) * ASTG_B;
        const int k0 = kt * 32;
        {   // K: 32 rows(t) x 8 segs, hi + lo
            int row = tid >> 3, seg = tid & 7;
            uint32_t so = (uint32_t)(row * PITCHQ + seg * 16);
            size_t gk = ((size_t)bh * Tt + k0 + row) * HD + seg * 8;
            cpa16(base + so,        g_Kh + gk);
            cpa16(base + KT_B + so, g_Kl + gk);
        }
        {   // V^T: 64 rows(d) x 4 segs, single fp16
            int row = tid >> 2, seg = tid & 3;
            uint32_t so = (uint32_t)(row * 80 + seg * 16);
            size_t gv = ((size_t)bh * HD + row) * Tt + k0 + seg * 8;
            cpa16(base + 2 * KT_B + so, g_Vt + gv);
        }
        CP_COMMIT();
    };

    loadKV(0);
    loadKV(1);
    loadKV(2);

    float m0r = -1e30f, m1r = -1e30f, l0r = 0.f, l1r = 0.f;
    float accO[8][4];
#pragma unroll
    for (int na = 0; na < 8; na++)
#pragma unroll
        for (int j = 0; j < 4; j++) accO[na][j] = 0.f;

    for (int kt = 0; kt < n_kv; kt++) {
        if (kt + 2 < n_kv)      { CP_WAIT(2); }
        else if (kt + 1 < n_kv) { CP_WAIT(1); }
        else                    { CP_WAIT(0); }
        __syncthreads();

        const uint32_t base = sT0 + (kt % 3) * ASTG_B;
        const int k0 = kt * 32;

        // ---- S = Q K^T (128x32): main fp32, corrections fp16 ----
        float s[4][4];
        uint32_t sc[4][2];
#pragma unroll
        for (int na = 0; na < 4; na++) {
#pragma unroll
            for (int j = 0; j < 4; j++) s[na][j] = 0.f;
            sc[na][0] = 0u; sc[na][1] = 0u;
        }

#pragma unroll
        for (int ks = 0; ks < 4; ks++) {
            const uint32_t qo = (uint32_t)((w * 16 + arow) * PITCHQ) + ks * 32 + akb;
            uint32_t qh[4], ql[4], kh[2][4], kl[2][4];
            ldsm_x4(qh[0], qh[1], qh[2], qh[3], sQh + qo);
            ldsm_x4(ql[0], ql[1], ql[2], ql[3], sQl + qo);
#pragma unroll
            for (int pb = 0; pb < 2; pb++) {
                uint32_t bo = (uint32_t)((pb * 16 + brow) * PITCHQ) + ks * 32 + bkb;
                ldsm_x4(kh[pb][0], kh[pb][1], kh[pb][2], kh[pb][3], base + bo);
                ldsm_x4(kl[pb][0], kl[pb][1], kl[pb][2], kl[pb][3], base + KT_B + bo);
            }
#pragma unroll
            for (int na = 0; na < 4; na++)
                mma_ff32(s[na], qh, kh[na >> 1][(na & 1) * 2], kh[na >> 1][(na & 1) * 2 + 1]);
#pragma unroll
            for (int na = 0; na < 4; na++)
                mma_ff16(sc[na], ql, kh[na >> 1][(na & 1) * 2], kh[na >> 1][(na & 1) * 2 + 1]);
#pragma unroll
            for (int na = 0; na < 4; na++)
                mma_ff16(sc[na], qh, kl[na >> 1][(na & 1) * 2], kl[na >> 1][(na & 1) * 2 + 1]);
        }
        // merge corrections
#pragma unroll
        for (int na = 0; na < 4; na++) {
            s[na][0] += h2lo(sc[na][0]);
            s[na][1] += h2hi(sc[na][0]);
            s[na][2] += h2lo(sc[na][1]);
            s[na][3] += h2hi(sc[na][1]);
        }

        // ---- causal mask ----
        const int r0 = q0 + w * 16 + gid, r1 = r0 + 8;
        if (k0 + 31 > r0) {
#pragma unroll
            for (int na = 0; na < 4; na++) {
                int c0 = k0 + na * 8 + tig * 2, c1 = c0 + 1;
                if (c0 > r0) s[na][0] = -1e30f;
                if (c1 > r0) s[na][1] = -1e30f;
                if (c0 > r1) s[na][2] = -1e30f;
                if (c1 > r1) s[na][3] = -1e30f;
            }
        }

        // ---- online softmax (base 2) ----
        float mx0 = -1e30f, mx1 = -1e30f;
#pragma unroll
        for (int na = 0; na < 4; na++) {
            mx0 = fmaxf(mx0, fmaxf(s[na][0], s[na][1]));
            mx1 = fmaxf(mx1, fmaxf(s[na][2], s[na][3]));
        }
        mx0 = fmaxf(mx0, __shfl_xor_sync(0xffffffffu, mx0, 1));
        mx0 = fmaxf(mx0, __shfl_xor_sync(0xffffffffu, mx0, 2));
        mx1 = fmaxf(mx1, __shfl_xor_sync(0xffffffffu, mx1, 1));
        mx1 = fmaxf(mx1, __shfl_xor_sync(0xffffffffu, mx1, 2));
        float mn0 = fmaxf(m0r, mx0), mn1 = fmaxf(m1r, mx1);
        float c0f = exp2f(m0r - mn0), c1f = exp2f(m1r - mn1);
        m0r = mn0; m1r = mn1;

        float rs0 = 0.f, rs1 = 0.f;
        uint32_t pa[4], pb2[4];       // P fp16 packs: rows gid / gid+8
#pragma unroll
        for (int na = 0; na < 4; na++) {
            float p0 = exp2f(s[na][0] - mn0);
            float p1 = exp2f(s[na][1] - mn0);
            float p2 = exp2f(s[na][2] - mn1);
            float p3 = exp2f(s[na][3] - mn1);
            rs0 += p0 + p1; rs1 += p2 + p3;
            pa[na]  = packh2(p0, p1);
            pb2[na] = packh2(p2, p3);
        }
        rs0 += __shfl_xor_sync(0xffffffffu, rs0, 1);
        rs0 += __shfl_xor_sync(0xffffffffu, rs0, 2);
        rs1 += __shfl_xor_sync(0xffffffffu, rs1, 1);
        rs1 += __shfl_xor_sync(0xffffffffu, rs1, 2);
        l0r = l0r * c0f + rs0;
        l1r = l1r * c1f + rs1;
#pragma unroll
        for (int na = 0; na < 8; na++) {
            accO[na][0] *= c0f; accO[na][1] *= c0f;
            accO[na][2] *= c1f; accO[na][3] *= c1f;
        }

        // ---- O += P V  (single product, P & V fp16) ----
        const uint32_t vb = base + 2 * KT_B;
#pragma unroll
        for (int ks = 0; ks < 2; ks++) {
            uint32_t vh[4][4];
#pragma unroll
            for (int pb = 0; pb < 4; pb++) {
                uint32_t bo = (uint32_t)((pb * 16 + brow) * 80) + ks * 32 + bkb;
                ldsm_x4(vh[pb][0], vh[pb][1], vh[pb][2], vh[pb][3], vb + bo);
            }
            uint32_t a_p[4] = {pa[2 * ks], pb2[2 * ks], pa[2 * ks + 1], pb2[2 * ks + 1]};
#pragma unroll
            for (int na = 0; na < 8; na++)
                mma_ff32(accO[na], a_p, vh[na >> 1][(na & 1) * 2],
                                        vh[na >> 1][(na & 1) * 2 + 1]);
        }

        if (kt + 3 < n_kv) {
            __syncthreads();      // ring slot (kt%3) free across all warps
            loadKV(kt + 3);
        }
    }

    // ---- epilogue ----
    const int b = bh >> 4, hh = bh & 15;
    const float inv0 = 1.0f / l0r, inv1 = 1.0f / l1r;
    const int r0 = q0 + w * 16 + gid, r1 = r0 + 8;
#pragma unroll
    for (int na = 0; na < 8; na++) {
        const int col = hh * 64 + na * 8 + tig * 2;
        float2 o0 = make_float2(accO[na][0] * inv0, accO[na][1] * inv0);
        float2 o1 = make_float2(accO[na][2] * inv1, accO[na][3] * inv1);
        *(float2*)&out[((size_t)(b * Tt + r0)) * Dm + col] = o0;
        *(float2*)&out[((size_t)(b * Tt + r1)) * Dm + col] = o1;
    }
}

// ---------------------------------------------------------------------------
extern "C" void kernel_launch(void* const* d_in, const int* in_sizes, int n_in,
                              void* d_out, int out_size)
{
    (void)in_sizes; (void)n_in; (void)out_size;
    const float* x  = (const float*)d_in[0];
    const float* Wq = (const float*)d_in[1];
    const float* bq = (const float*)d_in[2];
    const float* Wk = (const float*)d_in[3];
    const float* bk = (const float*)d_in[4];
    const float* Wv = (const float*)d_in[5];
    const float* bv = (const float*)d_in[6];
    float* out = (float*)d_out;

    const int nblk = (NX4 + 3 * NW4) / 256;     // 11264
    split_all<<<nblk, 256>>>(x, Wq, Wk, Wv);

    cudaFuncSetAttribute(proj_mma_kernel,
                         cudaFuncAttributeMaxDynamicSharedMemorySize, GEMM_SMEM);
    dim3 pg(Mtot / 128, Dm / 128, 3);
    proj_mma_kernel<<<pg, 256, GEMM_SMEM>>>(bq, bk, bv);

    cudaFuncSetAttribute(attn_mma_kernel,
                         cudaFuncAttributeMaxDynamicSharedMemorySize, ATTN_SMEM);
    attn_mma_kernel<<<dim3(16, 64), 256, ATTN_SMEM>>>(out);
}